// round 4
// baseline (speedup 1.0000x reference)
#include <cuda_runtime.h>
#include <cuda_bf16.h>
#include <math.h>
#include <stdint.h>

#define NN 1024   // tokens
#define DD 1024   // model dim
#define HH 16     // heads
#define CC 64     // chunk size
#define GG 16     // num chunks

// ---------------- scratch (device globals; no allocation allowed) ----------
__device__ __align__(16) float d_Q[NN * DD];
__device__ __align__(16) float d_K[NN * DD];
__device__ __align__(16) float d_V[NN * DD];
__device__ __align__(16) float d_GL[NN * 32];
__device__ __align__(16) float d_KC[GG * DD];
__device__ __align__(16) float d_O[NN * DD];

__device__ __align__(16) __nv_bfloat16 sx_hi[NN * DD], sx_lo[NN * DD];
__device__ __align__(16) __nv_bfloat16 swq_hi[DD * DD], swq_lo[DD * DD];
__device__ __align__(16) __nv_bfloat16 swk_hi[DD * DD], swk_lo[DD * DD];
__device__ __align__(16) __nv_bfloat16 swv_hi[DD * DD], swv_lo[DD * DD];
__device__ __align__(16) __nv_bfloat16 swo_hi[DD * DD], swo_lo[DD * DD];
__device__ __align__(16) __nv_bfloat16 swg_hi[32 * DD], swg_lo[32 * DD];
__device__ __align__(16) __nv_bfloat16 so_hi[NN * DD], so_lo[NN * DD];

// ---------------- helpers ----------------------------------------------------
__device__ __forceinline__ uint32_t smem_u32(const void* p) {
    uint32_t a;
    asm("{ .reg .u64 t; cvta.to.shared.u64 t, %1; cvt.u32.u64 %0, t; }" : "=r"(a) : "l"(p));
    return a;
}
__device__ __forceinline__ void ldsm_x4(uint32_t* r, uint32_t addr) {
    asm volatile("ldmatrix.sync.aligned.m8n8.x4.shared.b16 {%0,%1,%2,%3}, [%4];"
                 : "=r"(r[0]), "=r"(r[1]), "=r"(r[2]), "=r"(r[3]) : "r"(addr));
}
__device__ __forceinline__ void ldsm_x2(uint32_t* r, uint32_t addr) {
    asm volatile("ldmatrix.sync.aligned.m8n8.x2.shared.b16 {%0,%1}, [%2];"
                 : "=r"(r[0]), "=r"(r[1]) : "r"(addr));
}
__device__ __forceinline__ void mma16816(float* d, const uint32_t* a, const uint32_t* b) {
    asm volatile(
        "mma.sync.aligned.m16n8k16.row.col.f32.bf16.bf16.f32 "
        "{%0,%1,%2,%3}, {%4,%5,%6,%7}, {%8,%9}, {%0,%1,%2,%3};"
        : "+f"(d[0]), "+f"(d[1]), "+f"(d[2]), "+f"(d[3])
        : "r"(a[0]), "r"(a[1]), "r"(a[2]), "r"(a[3]), "r"(b[0]), "r"(b[1]));
}

// ---------------- fp32 -> bf16 hi/lo split conversion -----------------------
struct ConvArgs {
    const float* src[6];
    __nv_bfloat16* hi[6];
    __nv_bfloat16* lo[6];
    int n[6];
};

__global__ void convert_kernel(ConvArgs a) {
    int z = blockIdx.y;
    int i4 = (blockIdx.x * blockDim.x + threadIdx.x) * 4;
    if (i4 >= a.n[z]) return;
    float4 v = *(const float4*)(a.src[z] + i4);
    __nv_bfloat16 h0 = __float2bfloat16_rn(v.x);
    __nv_bfloat16 h1 = __float2bfloat16_rn(v.y);
    __nv_bfloat16 h2 = __float2bfloat16_rn(v.z);
    __nv_bfloat16 h3 = __float2bfloat16_rn(v.w);
    __nv_bfloat16 l0 = __float2bfloat16_rn(v.x - __bfloat162float(h0));
    __nv_bfloat16 l1 = __float2bfloat16_rn(v.y - __bfloat162float(h1));
    __nv_bfloat16 l2 = __float2bfloat16_rn(v.z - __bfloat162float(h2));
    __nv_bfloat16 l3 = __float2bfloat16_rn(v.w - __bfloat162float(h3));
    uint2 hp, lp;
    hp.x = (uint32_t)__bfloat16_as_ushort(h0) | ((uint32_t)__bfloat16_as_ushort(h1) << 16);
    hp.y = (uint32_t)__bfloat16_as_ushort(h2) | ((uint32_t)__bfloat16_as_ushort(h3) << 16);
    lp.x = (uint32_t)__bfloat16_as_ushort(l0) | ((uint32_t)__bfloat16_as_ushort(l1) << 16);
    lp.y = (uint32_t)__bfloat16_as_ushort(l2) | ((uint32_t)__bfloat16_as_ushort(l3) << 16);
    *(uint2*)(a.hi[z] + i4) = hp;
    *(uint2*)(a.lo[z] + i4) = lp;
}

// ---------------- HMMA GEMM: C[M,Nz] = A[M,K] @ B[Nz,K]^T -------------------
// bf16x3 emulation: C = Ah*Bh + Ah*Bl + Al*Bh, fp32 accumulators.
// 128x128 CTA tile, 8 warps (2x4), warp tile 64x32, mma.sync m16n8k16.
struct GemmArgs {
    const __nv_bfloat16* Ahi;
    const __nv_bfloat16* Alo;
    const __nv_bfloat16* Bhi[4];
    const __nv_bfloat16* Blo[4];
    float* C[4];
    int N[4];
};

#define SPAD 40   // bf16 elements per smem row (32 data + 8 pad) -> 80B stride

__global__ void __launch_bounds__(256) mma_gemm(GemmArgs g) {
    const int z = blockIdx.z;
    const int Nz = g.N[z];
    const int bn = blockIdx.x * 128;
    if (bn >= Nz) return;
    const int bm = blockIdx.y * 128;
    const int ncols = (Nz - bn < 128) ? (Nz - bn) : 128;

    __shared__ __nv_bfloat16 As_h[128 * SPAD];
    __shared__ __nv_bfloat16 As_l[128 * SPAD];
    __shared__ __nv_bfloat16 Bs_h[128 * SPAD];
    __shared__ __nv_bfloat16 Bs_l[128 * SPAD];

    const int tid = threadIdx.x;
    const int wid = tid >> 5;
    const int lane = tid & 31;
    const int wm = wid >> 2;        // 0..1 -> 64-row slab
    const int wn = wid & 3;         // 0..3 -> 32-col slab
    const bool active = (wn * 32) < ncols;

    float acc[4][4][4];
#pragma unroll
    for (int mt = 0; mt < 4; ++mt)
#pragma unroll
        for (int nt = 0; nt < 4; ++nt)
#pragma unroll
            for (int e = 0; e < 4; ++e) acc[mt][nt][e] = 0.f;

    const __nv_bfloat16* Ah = g.Ahi + (size_t)bm * DD;
    const __nv_bfloat16* Al = g.Alo + (size_t)bm * DD;
    const __nv_bfloat16* Bh = g.Bhi[z] + (size_t)bn * DD;
    const __nv_bfloat16* Bl = g.Blo[z] + (size_t)bn * DD;

    const uint32_t sAh = smem_u32(As_h), sAl = smem_u32(As_l);
    const uint32_t sBh = smem_u32(Bs_h), sBl = smem_u32(Bs_l);

    // ldmatrix addressing (precomputed, bytes)
    const int a_row = wm * 64 + (lane & 15);
    const int a_kof = (lane >> 4) << 3;                  // 0 or 8
    const int b_row = wn * 32 + (lane & 7);
    const int b_kof = (lane & 8) ? 8 : 0;

    for (int k0 = 0; k0 < DD; k0 += 32) {
        // stage 4 tiles of 128x32 bf16
#pragma unroll
        for (int s = 0; s < 2; ++s) {
            int u = tid + s * 256;                        // 0..511
            int r = u >> 2, seg = (u & 3) << 3;           // seg in bf16 elems
            size_t go = (size_t)r * DD + k0 + seg;
            uint32_t so = (uint32_t)(r * SPAD + seg);
            *(uint4*)(As_h + so) = *(const uint4*)(Ah + go);
            *(uint4*)(As_l + so) = *(const uint4*)(Al + go);
            if (r < ncols) {
                *(uint4*)(Bs_h + so) = *(const uint4*)(Bh + go);
                *(uint4*)(Bs_l + so) = *(const uint4*)(Bl + go);
            }
        }
        __syncthreads();
        if (active) {
#pragma unroll
            for (int kk = 0; kk < 32; kk += 16) {
                uint32_t ah[4][4], al[4][4], bh[4][2], bl[4][2];
#pragma unroll
                for (int mt = 0; mt < 4; ++mt) {
                    uint32_t off = (uint32_t)(((a_row + mt * 16) * SPAD + kk + a_kof) * 2);
                    ldsm_x4(ah[mt], sAh + off);
                    ldsm_x4(al[mt], sAl + off);
                }
#pragma unroll
                for (int nt = 0; nt < 4; ++nt) {
                    uint32_t off = (uint32_t)(((b_row + nt * 8) * SPAD + kk + b_kof) * 2);
                    ldsm_x2(bh[nt], sBh + off);
                    ldsm_x2(bl[nt], sBl + off);
                }
#pragma unroll
                for (int mt = 0; mt < 4; ++mt)
#pragma unroll
                    for (int nt = 0; nt < 4; ++nt) {
                        mma16816(acc[mt][nt], ah[mt], bh[nt]);
                        mma16816(acc[mt][nt], ah[mt], bl[nt]);
                        mma16816(acc[mt][nt], al[mt], bh[nt]);
                    }
            }
        }
        __syncthreads();
    }

    // epilogue
    float* Cz = g.C[z];
#pragma unroll
    for (int mt = 0; mt < 4; ++mt) {
        int row0 = bm + wm * 64 + mt * 16 + (lane >> 2);
#pragma unroll
        for (int nt = 0; nt < 4; ++nt) {
            int col = bn + wn * 32 + nt * 8 + (lane & 3) * 2;
            if (col < Nz) {
                *(float2*)(Cz + (size_t)row0 * Nz + col) =
                    make_float2(acc[mt][nt][0], acc[mt][nt][1]);
                *(float2*)(Cz + (size_t)(row0 + 8) * Nz + col) =
                    make_float2(acc[mt][nt][2], acc[mt][nt][3]);
            }
        }
    }
}

// ---------------- k_compress ------------------------------------------------
__global__ void compress_kernel(const float* __restrict__ K, float* __restrict__ KC)
{
    int idx = blockIdx.x * blockDim.x + threadIdx.x;
    if (idx >= GG * DD) return;
    int g = idx >> 10;
    int d = idx & 1023;
    float s = 0.f;
#pragma unroll 8
    for (int c = 0; c < CC; ++c)
        s += K[(size_t)(g * CC + c) * DD + d];
    KC[idx] = s * (1.0f / 64.0f);
}

// ---------------- fused sparse attention (as in R1, passing) ----------------
__device__ __forceinline__ float wred_max(float v) {
#pragma unroll
    for (int o = 16; o > 0; o >>= 1)
        v = fmaxf(v, __shfl_xor_sync(0xffffffffu, v, o));
    return v;
}
__device__ __forceinline__ float wred_sum(float v) {
#pragma unroll
    for (int o = 16; o > 0; o >>= 1)
        v += __shfl_xor_sync(0xffffffffu, v, o);
    return v;
}

__global__ void attn_kernel(const float* __restrict__ Q, const float* __restrict__ K,
                            const float* __restrict__ V, const float* __restrict__ KC,
                            const float* __restrict__ GL, float* __restrict__ O)
{
    extern __shared__ float sm[];
    float* q_s  = sm;              // 64*64
    float* kc_s = q_s + 4096;      // 16*65
    float* k_sT = kc_s + 1040;     // 64*65
    float* v_s  = k_sT + 4160;     // 64*64
    float* p_s  = v_s + 4096;      // 8*64
    float* sc_s = p_s + 512;       // 8*16
    int*   sel0 = (int*)(sc_s + 128);
    int*   sel1 = sel0 + 64;
    int*   nmask = sel1 + 64;

    const int g = blockIdx.x;
    const int h = blockIdx.y;
    const int tid = threadIdx.x;
    const int w = tid >> 5;
    const int lane = tid & 31;
    const float scale = 0.125f;

    if (tid == 0) *nmask = 0;
    for (int e = tid; e < 64 * 64; e += 256) {
        int i = e >> 6, d = e & 63;
        q_s[e] = Q[(size_t)(g * 64 + i) * DD + h * 64 + d];
    }
    for (int e = tid; e < 16 * 64; e += 256) {
        int gp = e >> 6, d = e & 63;
        kc_s[gp * 65 + d] = KC[(size_t)gp * DD + h * 64 + d];
    }
    __syncthreads();

    for (int qq = 0; qq < 8; ++qq) {
        int qi = w * 8 + qq;
        int gp = lane & 15;
        int half = lane >> 4;
        float part = 0.f;
#pragma unroll
        for (int d = 0; d < 32; ++d)
            part = fmaf(q_s[qi * 64 + half * 32 + d], kc_s[gp * 65 + half * 32 + d], part);
        part += __shfl_xor_sync(0xffffffffu, part, 16);
        if (lane < 16) sc_s[w * 16 + lane] = part;
        __syncwarp();
        float m1 = -INFINITY; int i1 = 0;
#pragma unroll
        for (int gp2 = 0; gp2 < 16; ++gp2) {
            float v = (gp2 > g) ? sc_s[w * 16 + gp2] : -INFINITY;
            if (v > m1) { m1 = v; i1 = gp2; }
        }
        float m2 = -INFINITY; int i2 = (i1 == 0) ? 1 : 0;
#pragma unroll
        for (int gp2 = 0; gp2 < 16; ++gp2) {
            if (gp2 == i1) continue;
            float v = (gp2 > g) ? sc_s[w * 16 + gp2] : -INFINITY;
            if (v > m2) { m2 = v; i2 = gp2; }
        }
        if (lane == 0) {
            sel0[qi] = i1; sel1[qi] = i2;
            atomicOr(nmask, (1 << i1) | (1 << i2));
        }
        __syncwarp();
    }
    __syncthreads();
    const int needed = *nmask;

    float accI0[8], accI1[8], mI[8], lI[8];
#pragma unroll
    for (int qq = 0; qq < 8; ++qq) {
        accI0[qq] = 0.f; accI1[qq] = 0.f; mI[qq] = -INFINITY; lI[qq] = 0.f;
    }

    for (int jb = 0; jb < 16; ++jb) {
        if (!(needed & (1 << jb))) continue;
        __syncthreads();
        for (int e = tid; e < 64 * 64; e += 256) {
            int c = e >> 6, d = e & 63;
            k_sT[d * 65 + c] = K[(size_t)(jb * 64 + c) * DD + h * 64 + d];
            v_s[c * 64 + d]  = V[(size_t)(jb * 64 + c) * DD + h * 64 + d];
        }
        __syncthreads();
        for (int qq = 0; qq < 8; ++qq) {
            int qi = w * 8 + qq;
            if (sel0[qi] != jb && sel1[qi] != jb) continue;
            float lg0 = 0.f, lg1 = 0.f;
#pragma unroll
            for (int d = 0; d < 64; ++d) {
                float qv = q_s[qi * 64 + d];
                lg0 = fmaf(qv, k_sT[d * 65 + lane], lg0);
                lg1 = fmaf(qv, k_sT[d * 65 + lane + 32], lg1);
            }
            lg0 *= scale; lg1 *= scale;
            float mn = wred_max(fmaxf(lg0, lg1));
            mn = fmaxf(mn, mI[qq]);
            float alpha = expf(mI[qq] - mn);
            float p0 = expf(lg0 - mn), p1 = expf(lg1 - mn);
            float ps = wred_sum(p0 + p1);
            lI[qq] = lI[qq] * alpha + ps;
            mI[qq] = mn;
            p_s[w * 64 + lane] = p0;
            p_s[w * 64 + lane + 32] = p1;
            __syncwarp();
            float a0 = accI0[qq] * alpha, a1 = accI1[qq] * alpha;
#pragma unroll
            for (int kk = 0; kk < 64; ++kk) {
                float p = p_s[w * 64 + kk];
                a0 = fmaf(p, v_s[kk * 64 + lane], a0);
                a1 = fmaf(p, v_s[kk * 64 + lane + 32], a1);
            }
            accI0[qq] = a0; accI1[qq] = a1;
            __syncwarp();
        }
    }

    __syncthreads();
    for (int e = tid; e < 64 * 64; e += 256) {
        int c = e >> 6, d = e & 63;
        k_sT[d * 65 + c] = K[(size_t)(g * 64 + c) * DD + h * 64 + d];
        v_s[c * 64 + d]  = V[(size_t)(g * 64 + c) * DD + h * 64 + d];
    }
    __syncthreads();
    for (int qq = 0; qq < 8; ++qq) {
        int qi = w * 8 + qq;
        float lg0 = 0.f, lg1 = 0.f;
#pragma unroll
        for (int d = 0; d < 64; ++d) {
            float qv = q_s[qi * 64 + d];
            lg0 = fmaf(qv, k_sT[d * 65 + lane], lg0);
            lg1 = fmaf(qv, k_sT[d * 65 + lane + 32], lg1);
        }
        lg0 = (lane      <= qi) ? lg0 * scale : -INFINITY;
        lg1 = (lane + 32 <= qi) ? lg1 * scale : -INFINITY;
        float mn = wred_max(fmaxf(lg0, lg1));
        float p0 = expf(lg0 - mn), p1 = expf(lg1 - mn);
        float ps = wred_sum(p0 + p1);
        p_s[w * 64 + lane] = p0;
        p_s[w * 64 + lane + 32] = p1;
        __syncwarp();
        float a0 = 0.f, a1 = 0.f;
#pragma unroll
        for (int kk = 0; kk < 64; ++kk) {
            float p = p_s[w * 64 + kk];
            a0 = fmaf(p, v_s[kk * 64 + lane], a0);
            a1 = fmaf(p, v_s[kk * 64 + lane + 32], a1);
        }
        __syncwarp();

        int n = g * 64 + qi;
        float gl0 = GL[(size_t)n * 32 + 2 * h];
        float gl1 = GL[(size_t)n * 32 + 2 * h + 1];
        float mg = fmaxf(gl0, gl1);
        float e0 = expf(gl0 - mg), e1 = expf(gl1 - mg);
        float ginv = 1.f / (e0 + e1);
        float g0 = e0 * ginv, g1 = e1 * ginv;
        float invI = 1.f / lI[qq];
        float invA = 1.f / ps;
        O[(size_t)n * DD + h * 64 + lane]      = g0 * accI0[qq] * invI + g1 * a0 * invA;
        O[(size_t)n * DD + h * 64 + lane + 32] = g0 * accI1[qq] * invI + g1 * a1 * invA;
    }
}

// ---------------- launch -----------------------------------------------------
extern "C" void kernel_launch(void* const* d_in, const int* in_sizes, int n_in,
                              void* d_out, int out_size)
{
    const float* x  = (const float*)d_in[0];
    const float* Wq = (const float*)d_in[1];
    const float* Wk = (const float*)d_in[2];
    const float* Wv = (const float*)d_in[3];
    const float* Wg = (const float*)d_in[4];
    const float* Wo = (const float*)d_in[5];
    float* out = (float*)d_out;

    float *Q, *K, *V, *GL, *KC, *O;
    cudaGetSymbolAddress((void**)&Q,  d_Q);
    cudaGetSymbolAddress((void**)&K,  d_K);
    cudaGetSymbolAddress((void**)&V,  d_V);
    cudaGetSymbolAddress((void**)&GL, d_GL);
    cudaGetSymbolAddress((void**)&KC, d_KC);
    cudaGetSymbolAddress((void**)&O,  d_O);

    __nv_bfloat16 *xh, *xl, *qh, *ql, *kh, *kl, *vh, *vl, *oh, *ol, *gh, *gl2, *obh, *obl;
    cudaGetSymbolAddress((void**)&xh,  sx_hi);  cudaGetSymbolAddress((void**)&xl,  sx_lo);
    cudaGetSymbolAddress((void**)&qh,  swq_hi); cudaGetSymbolAddress((void**)&ql,  swq_lo);
    cudaGetSymbolAddress((void**)&kh,  swk_hi); cudaGetSymbolAddress((void**)&kl,  swk_lo);
    cudaGetSymbolAddress((void**)&vh,  swv_hi); cudaGetSymbolAddress((void**)&vl,  swv_lo);
    cudaGetSymbolAddress((void**)&oh,  swo_hi); cudaGetSymbolAddress((void**)&ol,  swo_lo);
    cudaGetSymbolAddress((void**)&gh,  swg_hi); cudaGetSymbolAddress((void**)&gl2, swg_lo);
    cudaGetSymbolAddress((void**)&obh, so_hi);  cudaGetSymbolAddress((void**)&obl, so_lo);

    // 1) split-convert x + all weights
    ConvArgs ca;
    ca.src[0] = x;  ca.hi[0] = xh;  ca.lo[0] = xl;  ca.n[0] = NN * DD;
    ca.src[1] = Wq; ca.hi[1] = qh;  ca.lo[1] = ql;  ca.n[1] = DD * DD;
    ca.src[2] = Wk; ca.hi[2] = kh;  ca.lo[2] = kl;  ca.n[2] = DD * DD;
    ca.src[3] = Wv; ca.hi[3] = vh;  ca.lo[3] = vl;  ca.n[3] = DD * DD;
    ca.src[4] = Wg; ca.hi[4] = gh;  ca.lo[4] = gl2; ca.n[4] = 32 * DD;
    ca.src[5] = Wo; ca.hi[5] = oh;  ca.lo[5] = ol;  ca.n[5] = DD * DD;
    convert_kernel<<<dim3(1024, 6), 256>>>(ca);

    // 2) QKV + gate projections, one launch
    GemmArgs gq;
    gq.Ahi = xh; gq.Alo = xl;
    gq.Bhi[0] = qh; gq.Blo[0] = ql;  gq.C[0] = Q;  gq.N[0] = DD;
    gq.Bhi[1] = kh; gq.Blo[1] = kl;  gq.C[1] = K;  gq.N[1] = DD;
    gq.Bhi[2] = vh; gq.Blo[2] = vl;  gq.C[2] = V;  gq.N[2] = DD;
    gq.Bhi[3] = gh; gq.Blo[3] = gl2; gq.C[3] = GL; gq.N[3] = 32;
    mma_gemm<<<dim3(8, 8, 4), 256>>>(gq);

    // 3) compressed block keys
    compress_kernel<<<(GG * DD + 255) / 256, 256>>>(K, KC);

    // 4) fused sparse attention
    const int ASMEM = 57344;
    cudaFuncSetAttribute(attn_kernel, cudaFuncAttributeMaxDynamicSharedMemorySize, ASMEM);
    attn_kernel<<<dim3(GG, HH), 256, ASMEM>>>(Q, K, V, KC, GL, O);

    // 5) split-convert O
    ConvArgs co;
    co.src[0] = O; co.hi[0] = obh; co.lo[0] = obl; co.n[0] = NN * DD;
    for (int i = 1; i < 6; ++i) { co.src[i] = O; co.hi[i] = obh; co.lo[i] = obl; co.n[i] = 0; }
    convert_kernel<<<dim3(1024, 1), 256>>>(co);

    // 6) output projection
    GemmArgs go;
    go.Ahi = obh; go.Alo = obl;
    go.Bhi[0] = oh; go.Blo[0] = ol; go.C[0] = out; go.N[0] = DD;
    for (int i = 1; i < 4; ++i) { go.Bhi[i] = oh; go.Blo[i] = ol; go.C[i] = out; go.N[i] = 0; }
    mma_gemm<<<dim3(8, 8, 1), 256>>>(go);
}

// round 5
// speedup vs baseline: 1.0013x; 1.0013x over previous
#include <cuda_runtime.h>
#include <cuda_bf16.h>
#include <math.h>
#include <stdint.h>

#define NN 1024   // tokens
#define DD 1024   // model dim
#define HH 16     // heads
#define CC 64     // chunk size
#define GG 16     // num chunks

// ---------------- scratch (device globals; no allocation allowed) ----------
__device__ __align__(16) float d_Q[NN * DD];
__device__ __align__(16) float d_K[NN * DD];
__device__ __align__(16) float d_V[NN * DD];
__device__ __align__(16) float d_GL[NN * 32];
__device__ __align__(16) float d_KC[GG * DD];
__device__ __align__(16) float d_O[NN * DD];

__device__ __align__(16) __nv_bfloat16 sx_hi[NN * DD], sx_lo[NN * DD];
__device__ __align__(16) __nv_bfloat16 swq_hi[DD * DD], swq_lo[DD * DD];
__device__ __align__(16) __nv_bfloat16 swk_hi[DD * DD], swk_lo[DD * DD];
__device__ __align__(16) __nv_bfloat16 swv_hi[DD * DD], swv_lo[DD * DD];
__device__ __align__(16) __nv_bfloat16 swo_hi[DD * DD], swo_lo[DD * DD];
__device__ __align__(16) __nv_bfloat16 swg_hi[32 * DD], swg_lo[32 * DD];
__device__ __align__(16) __nv_bfloat16 so_hi[NN * DD], so_lo[NN * DD];

// ---------------- helpers ----------------------------------------------------
__device__ __forceinline__ uint32_t smem_u32(const void* p) {
    uint32_t a;
    asm("{ .reg .u64 t; cvta.to.shared.u64 t, %1; cvt.u32.u64 %0, t; }" : "=r"(a) : "l"(p));
    return a;
}
__device__ __forceinline__ void ldsm_x4(uint32_t* r, uint32_t addr) {
    asm volatile("ldmatrix.sync.aligned.m8n8.x4.shared.b16 {%0,%1,%2,%3}, [%4];"
                 : "=r"(r[0]), "=r"(r[1]), "=r"(r[2]), "=r"(r[3]) : "r"(addr));
}
__device__ __forceinline__ void ldsm_x2(uint32_t* r, uint32_t addr) {
    asm volatile("ldmatrix.sync.aligned.m8n8.x2.shared.b16 {%0,%1}, [%2];"
                 : "=r"(r[0]), "=r"(r[1]) : "r"(addr));
}
__device__ __forceinline__ void mma16816(float* d, const uint32_t* a, const uint32_t* b) {
    asm volatile(
        "mma.sync.aligned.m16n8k16.row.col.f32.bf16.bf16.f32 "
        "{%0,%1,%2,%3}, {%4,%5,%6,%7}, {%8,%9}, {%0,%1,%2,%3};"
        : "+f"(d[0]), "+f"(d[1]), "+f"(d[2]), "+f"(d[3])
        : "r"(a[0]), "r"(a[1]), "r"(a[2]), "r"(a[3]), "r"(b[0]), "r"(b[1]));
}

// ---------------- fp32 -> bf16 hi/lo split conversion -----------------------
struct ConvArgs {
    const float* src[6];
    __nv_bfloat16* hi[6];
    __nv_bfloat16* lo[6];
    int n[6];
};

__global__ void convert_kernel(ConvArgs a) {
    int z = blockIdx.y;
    int i4 = (blockIdx.x * blockDim.x + threadIdx.x) * 4;
    if (i4 >= a.n[z]) return;
    float4 v = *(const float4*)(a.src[z] + i4);
    __nv_bfloat16 h0 = __float2bfloat16_rn(v.x);
    __nv_bfloat16 h1 = __float2bfloat16_rn(v.y);
    __nv_bfloat16 h2 = __float2bfloat16_rn(v.z);
    __nv_bfloat16 h3 = __float2bfloat16_rn(v.w);
    __nv_bfloat16 l0 = __float2bfloat16_rn(v.x - __bfloat162float(h0));
    __nv_bfloat16 l1 = __float2bfloat16_rn(v.y - __bfloat162float(h1));
    __nv_bfloat16 l2 = __float2bfloat16_rn(v.z - __bfloat162float(h2));
    __nv_bfloat16 l3 = __float2bfloat16_rn(v.w - __bfloat162float(h3));
    uint2 hp, lp;
    hp.x = (uint32_t)__bfloat16_as_ushort(h0) | ((uint32_t)__bfloat16_as_ushort(h1) << 16);
    hp.y = (uint32_t)__bfloat16_as_ushort(h2) | ((uint32_t)__bfloat16_as_ushort(h3) << 16);
    lp.x = (uint32_t)__bfloat16_as_ushort(l0) | ((uint32_t)__bfloat16_as_ushort(l1) << 16);
    lp.y = (uint32_t)__bfloat16_as_ushort(l2) | ((uint32_t)__bfloat16_as_ushort(l3) << 16);
    *(uint2*)(a.hi[z] + i4) = hp;
    *(uint2*)(a.lo[z] + i4) = lp;
}

// ---------------- HMMA GEMM: C[M,Nz] = A[M,K] @ B[Nz,K]^T -------------------
// bf16x3 emulation: C = Ah*Bh + Ah*Bl + Al*Bh, fp32 accumulators.
// 128x128 CTA tile, 8 warps (2x4), warp tile 64x32, mma.sync m16n8k16.
struct GemmArgs {
    const __nv_bfloat16* Ahi;
    const __nv_bfloat16* Alo;
    const __nv_bfloat16* Bhi[4];
    const __nv_bfloat16* Blo[4];
    float* C[4];
    int N[4];
};

#define SPAD 40   // bf16 elements per smem row (32 data + 8 pad) -> 80B stride

__global__ void __launch_bounds__(256) mma_gemm(GemmArgs g) {
    const int z = blockIdx.z;
    const int Nz = g.N[z];
    const int bn = blockIdx.x * 128;
    if (bn >= Nz) return;
    const int bm = blockIdx.y * 128;
    const int ncols = (Nz - bn < 128) ? (Nz - bn) : 128;

    __shared__ __nv_bfloat16 As_h[128 * SPAD];
    __shared__ __nv_bfloat16 As_l[128 * SPAD];
    __shared__ __nv_bfloat16 Bs_h[128 * SPAD];
    __shared__ __nv_bfloat16 Bs_l[128 * SPAD];

    const int tid = threadIdx.x;
    const int wid = tid >> 5;
    const int lane = tid & 31;
    const int wm = wid >> 2;        // 0..1 -> 64-row slab
    const int wn = wid & 3;         // 0..3 -> 32-col slab
    const bool active = (wn * 32) < ncols;

    float acc[4][4][4];
#pragma unroll
    for (int mt = 0; mt < 4; ++mt)
#pragma unroll
        for (int nt = 0; nt < 4; ++nt)
#pragma unroll
            for (int e = 0; e < 4; ++e) acc[mt][nt][e] = 0.f;

    const __nv_bfloat16* Ah = g.Ahi + (size_t)bm * DD;
    const __nv_bfloat16* Al = g.Alo + (size_t)bm * DD;
    const __nv_bfloat16* Bh = g.Bhi[z] + (size_t)bn * DD;
    const __nv_bfloat16* Bl = g.Blo[z] + (size_t)bn * DD;

    const uint32_t sAh = smem_u32(As_h), sAl = smem_u32(As_l);
    const uint32_t sBh = smem_u32(Bs_h), sBl = smem_u32(Bs_l);

    // ldmatrix addressing (precomputed, bytes)
    const int a_row = wm * 64 + (lane & 15);
    const int a_kof = (lane >> 4) << 3;                  // 0 or 8
    const int b_row = wn * 32 + (lane & 7);
    const int b_kof = (lane & 8) ? 8 : 0;

    for (int k0 = 0; k0 < DD; k0 += 32) {
        // stage 4 tiles of 128x32 bf16
#pragma unroll
        for (int s = 0; s < 2; ++s) {
            int u = tid + s * 256;                        // 0..511
            int r = u >> 2, seg = (u & 3) << 3;           // seg in bf16 elems
            size_t go = (size_t)r * DD + k0 + seg;
            uint32_t so = (uint32_t)(r * SPAD + seg);
            *(uint4*)(As_h + so) = *(const uint4*)(Ah + go);
            *(uint4*)(As_l + so) = *(const uint4*)(Al + go);
            if (r < ncols) {
                *(uint4*)(Bs_h + so) = *(const uint4*)(Bh + go);
                *(uint4*)(Bs_l + so) = *(const uint4*)(Bl + go);
            }
        }
        __syncthreads();
        if (active) {
#pragma unroll
            for (int kk = 0; kk < 32; kk += 16) {
                uint32_t ah[4][4], al[4][4], bh[4][2], bl[4][2];
#pragma unroll
                for (int mt = 0; mt < 4; ++mt) {
                    uint32_t off = (uint32_t)(((a_row + mt * 16) * SPAD + kk + a_kof) * 2);
                    ldsm_x4(ah[mt], sAh + off);
                    ldsm_x4(al[mt], sAl + off);
                }
#pragma unroll
                for (int nt = 0; nt < 4; ++nt) {
                    uint32_t off = (uint32_t)(((b_row + nt * 8) * SPAD + kk + b_kof) * 2);
                    ldsm_x2(bh[nt], sBh + off);
                    ldsm_x2(bl[nt], sBl + off);
                }
#pragma unroll
                for (int mt = 0; mt < 4; ++mt)
#pragma unroll
                    for (int nt = 0; nt < 4; ++nt) {
                        mma16816(acc[mt][nt], ah[mt], bh[nt]);
                        mma16816(acc[mt][nt], ah[mt], bl[nt]);
                        mma16816(acc[mt][nt], al[mt], bh[nt]);
                    }
            }
        }
        __syncthreads();
    }

    // epilogue
    float* Cz = g.C[z];
#pragma unroll
    for (int mt = 0; mt < 4; ++mt) {
        int row0 = bm + wm * 64 + mt * 16 + (lane >> 2);
#pragma unroll
        for (int nt = 0; nt < 4; ++nt) {
            int col = bn + wn * 32 + nt * 8 + (lane & 3) * 2;
            if (col < Nz) {
                *(float2*)(Cz + (size_t)row0 * Nz + col) =
                    make_float2(acc[mt][nt][0], acc[mt][nt][1]);
                *(float2*)(Cz + (size_t)(row0 + 8) * Nz + col) =
                    make_float2(acc[mt][nt][2], acc[mt][nt][3]);
            }
        }
    }
}

// ---------------- k_compress ------------------------------------------------
__global__ void compress_kernel(const float* __restrict__ K, float* __restrict__ KC)
{
    int idx = blockIdx.x * blockDim.x + threadIdx.x;
    if (idx >= GG * DD) return;
    int g = idx >> 10;
    int d = idx & 1023;
    float s = 0.f;
#pragma unroll 8
    for (int c = 0; c < CC; ++c)
        s += K[(size_t)(g * CC + c) * DD + d];
    KC[idx] = s * (1.0f / 64.0f);
}

// ---------------- fused sparse attention (as in R1, passing) ----------------
__device__ __forceinline__ float wred_max(float v) {
#pragma unroll
    for (int o = 16; o > 0; o >>= 1)
        v = fmaxf(v, __shfl_xor_sync(0xffffffffu, v, o));
    return v;
}
__device__ __forceinline__ float wred_sum(float v) {
#pragma unroll
    for (int o = 16; o > 0; o >>= 1)
        v += __shfl_xor_sync(0xffffffffu, v, o);
    return v;
}

__global__ void attn_kernel(const float* __restrict__ Q, const float* __restrict__ K,
                            const float* __restrict__ V, const float* __restrict__ KC,
                            const float* __restrict__ GL, float* __restrict__ O)
{
    extern __shared__ float sm[];
    float* q_s  = sm;              // 64*64
    float* kc_s = q_s + 4096;      // 16*65
    float* k_sT = kc_s + 1040;     // 64*65
    float* v_s  = k_sT + 4160;     // 64*64
    float* p_s  = v_s + 4096;      // 8*64
    float* sc_s = p_s + 512;       // 8*16
    int*   sel0 = (int*)(sc_s + 128);
    int*   sel1 = sel0 + 64;
    int*   nmask = sel1 + 64;

    const int g = blockIdx.x;
    const int h = blockIdx.y;
    const int tid = threadIdx.x;
    const int w = tid >> 5;
    const int lane = tid & 31;
    const float scale = 0.125f;

    if (tid == 0) *nmask = 0;
    for (int e = tid; e < 64 * 64; e += 256) {
        int i = e >> 6, d = e & 63;
        q_s[e] = Q[(size_t)(g * 64 + i) * DD + h * 64 + d];
    }
    for (int e = tid; e < 16 * 64; e += 256) {
        int gp = e >> 6, d = e & 63;
        kc_s[gp * 65 + d] = KC[(size_t)gp * DD + h * 64 + d];
    }
    __syncthreads();

    for (int qq = 0; qq < 8; ++qq) {
        int qi = w * 8 + qq;
        int gp = lane & 15;
        int half = lane >> 4;
        float part = 0.f;
#pragma unroll
        for (int d = 0; d < 32; ++d)
            part = fmaf(q_s[qi * 64 + half * 32 + d], kc_s[gp * 65 + half * 32 + d], part);
        part += __shfl_xor_sync(0xffffffffu, part, 16);
        if (lane < 16) sc_s[w * 16 + lane] = part;
        __syncwarp();
        float m1 = -INFINITY; int i1 = 0;
#pragma unroll
        for (int gp2 = 0; gp2 < 16; ++gp2) {
            float v = (gp2 > g) ? sc_s[w * 16 + gp2] : -INFINITY;
            if (v > m1) { m1 = v; i1 = gp2; }
        }
        float m2 = -INFINITY; int i2 = (i1 == 0) ? 1 : 0;
#pragma unroll
        for (int gp2 = 0; gp2 < 16; ++gp2) {
            if (gp2 == i1) continue;
            float v = (gp2 > g) ? sc_s[w * 16 + gp2] : -INFINITY;
            if (v > m2) { m2 = v; i2 = gp2; }
        }
        if (lane == 0) {
            sel0[qi] = i1; sel1[qi] = i2;
            atomicOr(nmask, (1 << i1) | (1 << i2));
        }
        __syncwarp();
    }
    __syncthreads();
    const int needed = *nmask;

    float accI0[8], accI1[8], mI[8], lI[8];
#pragma unroll
    for (int qq = 0; qq < 8; ++qq) {
        accI0[qq] = 0.f; accI1[qq] = 0.f; mI[qq] = -INFINITY; lI[qq] = 0.f;
    }

    for (int jb = 0; jb < 16; ++jb) {
        if (!(needed & (1 << jb))) continue;
        __syncthreads();
        for (int e = tid; e < 64 * 64; e += 256) {
            int c = e >> 6, d = e & 63;
            k_sT[d * 65 + c] = K[(size_t)(jb * 64 + c) * DD + h * 64 + d];
            v_s[c * 64 + d]  = V[(size_t)(jb * 64 + c) * DD + h * 64 + d];
        }
        __syncthreads();
        for (int qq = 0; qq < 8; ++qq) {
            int qi = w * 8 + qq;
            if (sel0[qi] != jb && sel1[qi] != jb) continue;
            float lg0 = 0.f, lg1 = 0.f;
#pragma unroll
            for (int d = 0; d < 64; ++d) {
                float qv = q_s[qi * 64 + d];
                lg0 = fmaf(qv, k_sT[d * 65 + lane], lg0);
                lg1 = fmaf(qv, k_sT[d * 65 + lane + 32], lg1);
            }
            lg0 *= scale; lg1 *= scale;
            float mn = wred_max(fmaxf(lg0, lg1));
            mn = fmaxf(mn, mI[qq]);
            float alpha = expf(mI[qq] - mn);
            float p0 = expf(lg0 - mn), p1 = expf(lg1 - mn);
            float ps = wred_sum(p0 + p1);
            lI[qq] = lI[qq] * alpha + ps;
            mI[qq] = mn;
            p_s[w * 64 + lane] = p0;
            p_s[w * 64 + lane + 32] = p1;
            __syncwarp();
            float a0 = accI0[qq] * alpha, a1 = accI1[qq] * alpha;
#pragma unroll
            for (int kk = 0; kk < 64; ++kk) {
                float p = p_s[w * 64 + kk];
                a0 = fmaf(p, v_s[kk * 64 + lane], a0);
                a1 = fmaf(p, v_s[kk * 64 + lane + 32], a1);
            }
            accI0[qq] = a0; accI1[qq] = a1;
            __syncwarp();
        }
    }

    __syncthreads();
    for (int e = tid; e < 64 * 64; e += 256) {
        int c = e >> 6, d = e & 63;
        k_sT[d * 65 + c] = K[(size_t)(g * 64 + c) * DD + h * 64 + d];
        v_s[c * 64 + d]  = V[(size_t)(g * 64 + c) * DD + h * 64 + d];
    }
    __syncthreads();
    for (int qq = 0; qq < 8; ++qq) {
        int qi = w * 8 + qq;
        float lg0 = 0.f, lg1 = 0.f;
#pragma unroll
        for (int d = 0; d < 64; ++d) {
            float qv = q_s[qi * 64 + d];
            lg0 = fmaf(qv, k_sT[d * 65 + lane], lg0);
            lg1 = fmaf(qv, k_sT[d * 65 + lane + 32], lg1);
        }
        lg0 = (lane      <= qi) ? lg0 * scale : -INFINITY;
        lg1 = (lane + 32 <= qi) ? lg1 * scale : -INFINITY;
        float mn = wred_max(fmaxf(lg0, lg1));
        float p0 = expf(lg0 - mn), p1 = expf(lg1 - mn);
        float ps = wred_sum(p0 + p1);
        p_s[w * 64 + lane] = p0;
        p_s[w * 64 + lane + 32] = p1;
        __syncwarp();
        float a0 = 0.f, a1 = 0.f;
#pragma unroll
        for (int kk = 0; kk < 64; ++kk) {
            float p = p_s[w * 64 + kk];
            a0 = fmaf(p, v_s[kk * 64 + lane], a0);
            a1 = fmaf(p, v_s[kk * 64 + lane + 32], a1);
        }
        __syncwarp();

        int n = g * 64 + qi;
        float gl0 = GL[(size_t)n * 32 + 2 * h];
        float gl1 = GL[(size_t)n * 32 + 2 * h + 1];
        float mg = fmaxf(gl0, gl1);
        float e0 = expf(gl0 - mg), e1 = expf(gl1 - mg);
        float ginv = 1.f / (e0 + e1);
        float g0 = e0 * ginv, g1 = e1 * ginv;
        float invI = 1.f / lI[qq];
        float invA = 1.f / ps;
        O[(size_t)n * DD + h * 64 + lane]      = g0 * accI0[qq] * invI + g1 * a0 * invA;
        O[(size_t)n * DD + h * 64 + lane + 32] = g0 * accI1[qq] * invI + g1 * a1 * invA;
    }
}

// ---------------- launch -----------------------------------------------------
extern "C" void kernel_launch(void* const* d_in, const int* in_sizes, int n_in,
                              void* d_out, int out_size)
{
    const float* x  = (const float*)d_in[0];
    const float* Wq = (const float*)d_in[1];
    const float* Wk = (const float*)d_in[2];
    const float* Wv = (const float*)d_in[3];
    const float* Wg = (const float*)d_in[4];
    const float* Wo = (const float*)d_in[5];
    float* out = (float*)d_out;

    float *Q, *K, *V, *GL, *KC, *O;
    cudaGetSymbolAddress((void**)&Q,  d_Q);
    cudaGetSymbolAddress((void**)&K,  d_K);
    cudaGetSymbolAddress((void**)&V,  d_V);
    cudaGetSymbolAddress((void**)&GL, d_GL);
    cudaGetSymbolAddress((void**)&KC, d_KC);
    cudaGetSymbolAddress((void**)&O,  d_O);

    __nv_bfloat16 *xh, *xl, *qh, *ql, *kh, *kl, *vh, *vl, *oh, *ol, *gh, *gl2, *obh, *obl;
    cudaGetSymbolAddress((void**)&xh,  sx_hi);  cudaGetSymbolAddress((void**)&xl,  sx_lo);
    cudaGetSymbolAddress((void**)&qh,  swq_hi); cudaGetSymbolAddress((void**)&ql,  swq_lo);
    cudaGetSymbolAddress((void**)&kh,  swk_hi); cudaGetSymbolAddress((void**)&kl,  swk_lo);
    cudaGetSymbolAddress((void**)&vh,  swv_hi); cudaGetSymbolAddress((void**)&vl,  swv_lo);
    cudaGetSymbolAddress((void**)&oh,  swo_hi); cudaGetSymbolAddress((void**)&ol,  swo_lo);
    cudaGetSymbolAddress((void**)&gh,  swg_hi); cudaGetSymbolAddress((void**)&gl2, swg_lo);
    cudaGetSymbolAddress((void**)&obh, so_hi);  cudaGetSymbolAddress((void**)&obl, so_lo);

    // 1) split-convert x + all weights
    ConvArgs ca;
    ca.src[0] = x;  ca.hi[0] = xh;  ca.lo[0] = xl;  ca.n[0] = NN * DD;
    ca.src[1] = Wq; ca.hi[1] = qh;  ca.lo[1] = ql;  ca.n[1] = DD * DD;
    ca.src[2] = Wk; ca.hi[2] = kh;  ca.lo[2] = kl;  ca.n[2] = DD * DD;
    ca.src[3] = Wv; ca.hi[3] = vh;  ca.lo[3] = vl;  ca.n[3] = DD * DD;
    ca.src[4] = Wg; ca.hi[4] = gh;  ca.lo[4] = gl2; ca.n[4] = 32 * DD;
    ca.src[5] = Wo; ca.hi[5] = oh;  ca.lo[5] = ol;  ca.n[5] = DD * DD;
    convert_kernel<<<dim3(1024, 6), 256>>>(ca);

    // 2) QKV + gate projections, one launch
    GemmArgs gq;
    gq.Ahi = xh; gq.Alo = xl;
    gq.Bhi[0] = qh; gq.Blo[0] = ql;  gq.C[0] = Q;  gq.N[0] = DD;
    gq.Bhi[1] = kh; gq.Blo[1] = kl;  gq.C[1] = K;  gq.N[1] = DD;
    gq.Bhi[2] = vh; gq.Blo[2] = vl;  gq.C[2] = V;  gq.N[2] = DD;
    gq.Bhi[3] = gh; gq.Blo[3] = gl2; gq.C[3] = GL; gq.N[3] = 32;
    mma_gemm<<<dim3(8, 8, 4), 256>>>(gq);

    // 3) compressed block keys
    compress_kernel<<<(GG * DD + 255) / 256, 256>>>(K, KC);

    // 4) fused sparse attention
    const int ASMEM = 57344;
    cudaFuncSetAttribute(attn_kernel, cudaFuncAttributeMaxDynamicSharedMemorySize, ASMEM);
    attn_kernel<<<dim3(GG, HH), 256, ASMEM>>>(Q, K, V, KC, GL, O);

    // 5) split-convert O
    ConvArgs co;
    co.src[0] = O; co.hi[0] = obh; co.lo[0] = obl; co.n[0] = NN * DD;
    for (int i = 1; i < 6; ++i) { co.src[i] = O; co.hi[i] = obh; co.lo[i] = obl; co.n[i] = 0; }
    convert_kernel<<<dim3(1024, 1), 256>>>(co);

    // 6) output projection
    GemmArgs go;
    go.Ahi = obh; go.Alo = obl;
    go.Bhi[0] = oh; go.Blo[0] = ol; go.C[0] = out; go.N[0] = DD;
    for (int i = 1; i < 4; ++i) { go.Bhi[i] = oh; go.Blo[i] = ol; go.C[i] = out; go.N[i] = 0; }
    mma_gemm<<<dim3(8, 8, 1), 256>>>(go);
}

// round 6
// speedup vs baseline: 1.2145x; 1.2130x over previous
#include <cuda_runtime.h>
#include <cuda_bf16.h>
#include <math.h>
#include <stdint.h>

#define NN 1024   // tokens
#define DD 1024   // model dim
#define HH 16     // heads
#define CC 64     // chunk size
#define GG 16     // num chunks

// ---------------- scratch (device globals; no allocation allowed) ----------
__device__ __align__(16) float d_Q[NN * DD];
__device__ __align__(16) float d_K[NN * DD];
__device__ __align__(16) float d_V[NN * DD];
__device__ __align__(16) float d_GL[NN * 32];
__device__ __align__(16) float d_KC[GG * DD];
__device__ __align__(16) float d_O[NN * DD];

__device__ __align__(16) __nv_bfloat16 sx_hi[NN * DD], sx_lo[NN * DD];
__device__ __align__(16) __nv_bfloat16 swq_hi[DD * DD], swq_lo[DD * DD];
__device__ __align__(16) __nv_bfloat16 swk_hi[DD * DD], swk_lo[DD * DD];
__device__ __align__(16) __nv_bfloat16 swv_hi[DD * DD], swv_lo[DD * DD];
__device__ __align__(16) __nv_bfloat16 swo_hi[DD * DD], swo_lo[DD * DD];
__device__ __align__(16) __nv_bfloat16 swg_hi[32 * DD], swg_lo[32 * DD];
__device__ __align__(16) __nv_bfloat16 so_hi[NN * DD], so_lo[NN * DD];

// ---------------- helpers ----------------------------------------------------
__device__ __forceinline__ uint32_t smem_u32(const void* p) {
    uint32_t a;
    asm("{ .reg .u64 t; cvta.to.shared.u64 t, %1; cvt.u32.u64 %0, t; }" : "=r"(a) : "l"(p));
    return a;
}
__device__ __forceinline__ void ldsm_x4(uint32_t* r, uint32_t addr) {
    asm volatile("ldmatrix.sync.aligned.m8n8.x4.shared.b16 {%0,%1,%2,%3}, [%4];"
                 : "=r"(r[0]), "=r"(r[1]), "=r"(r[2]), "=r"(r[3]) : "r"(addr));
}
__device__ __forceinline__ void ldsm_x2(uint32_t* r, uint32_t addr) {
    asm volatile("ldmatrix.sync.aligned.m8n8.x2.shared.b16 {%0,%1}, [%2];"
                 : "=r"(r[0]), "=r"(r[1]) : "r"(addr));
}
__device__ __forceinline__ void mma16816(float* d, const uint32_t* a, const uint32_t* b) {
    asm volatile(
        "mma.sync.aligned.m16n8k16.row.col.f32.bf16.bf16.f32 "
        "{%0,%1,%2,%3}, {%4,%5,%6,%7}, {%8,%9}, {%0,%1,%2,%3};"
        : "+f"(d[0]), "+f"(d[1]), "+f"(d[2]), "+f"(d[3])
        : "r"(a[0]), "r"(a[1]), "r"(a[2]), "r"(a[3]), "r"(b[0]), "r"(b[1]));
}
__device__ __forceinline__ uint32_t packbf(float a, float b) {
    __nv_bfloat162 t;
    t.x = __float2bfloat16_rn(a);
    t.y = __float2bfloat16_rn(b);
    return *(uint32_t*)&t;
}

// ---------------- fp32 -> bf16 hi/lo split conversion -----------------------
struct ConvArgs {
    const float* src[6];
    __nv_bfloat16* hi[6];
    __nv_bfloat16* lo[6];
    int n[6];
};

__global__ void convert_kernel(ConvArgs a) {
    int z = blockIdx.y;
    int i4 = (blockIdx.x * blockDim.x + threadIdx.x) * 4;
    if (i4 >= a.n[z]) return;
    float4 v = *(const float4*)(a.src[z] + i4);
    __nv_bfloat16 h0 = __float2bfloat16_rn(v.x);
    __nv_bfloat16 h1 = __float2bfloat16_rn(v.y);
    __nv_bfloat16 h2 = __float2bfloat16_rn(v.z);
    __nv_bfloat16 h3 = __float2bfloat16_rn(v.w);
    __nv_bfloat16 l0 = __float2bfloat16_rn(v.x - __bfloat162float(h0));
    __nv_bfloat16 l1 = __float2bfloat16_rn(v.y - __bfloat162float(h1));
    __nv_bfloat16 l2 = __float2bfloat16_rn(v.z - __bfloat162float(h2));
    __nv_bfloat16 l3 = __float2bfloat16_rn(v.w - __bfloat162float(h3));
    uint2 hp, lp;
    hp.x = (uint32_t)__bfloat16_as_ushort(h0) | ((uint32_t)__bfloat16_as_ushort(h1) << 16);
    hp.y = (uint32_t)__bfloat16_as_ushort(h2) | ((uint32_t)__bfloat16_as_ushort(h3) << 16);
    lp.x = (uint32_t)__bfloat16_as_ushort(l0) | ((uint32_t)__bfloat16_as_ushort(l1) << 16);
    lp.y = (uint32_t)__bfloat16_as_ushort(l2) | ((uint32_t)__bfloat16_as_ushort(l3) << 16);
    *(uint2*)(a.hi[z] + i4) = hp;
    *(uint2*)(a.lo[z] + i4) = lp;
}

// ---------------- HMMA GEMM: C[M,Nz] = A[M,K] @ B[Nz,K]^T -------------------
struct GemmArgs {
    const __nv_bfloat16* Ahi;
    const __nv_bfloat16* Alo;
    const __nv_bfloat16* Bhi[4];
    const __nv_bfloat16* Blo[4];
    float* C[4];
    int N[4];
};

#define SPAD 40

__global__ void __launch_bounds__(256) mma_gemm(GemmArgs g) {
    const int z = blockIdx.z;
    const int Nz = g.N[z];
    const int bn = blockIdx.x * 128;
    if (bn >= Nz) return;
    const int bm = blockIdx.y * 128;
    const int ncols = (Nz - bn < 128) ? (Nz - bn) : 128;

    __shared__ __nv_bfloat16 As_h[128 * SPAD];
    __shared__ __nv_bfloat16 As_l[128 * SPAD];
    __shared__ __nv_bfloat16 Bs_h[128 * SPAD];
    __shared__ __nv_bfloat16 Bs_l[128 * SPAD];

    const int tid = threadIdx.x;
    const int wid = tid >> 5;
    const int lane = tid & 31;
    const int wm = wid >> 2;
    const int wn = wid & 3;
    const bool active = (wn * 32) < ncols;

    float acc[4][4][4];
#pragma unroll
    for (int mt = 0; mt < 4; ++mt)
#pragma unroll
        for (int nt = 0; nt < 4; ++nt)
#pragma unroll
            for (int e = 0; e < 4; ++e) acc[mt][nt][e] = 0.f;

    const __nv_bfloat16* Ah = g.Ahi + (size_t)bm * DD;
    const __nv_bfloat16* Al = g.Alo + (size_t)bm * DD;
    const __nv_bfloat16* Bh = g.Bhi[z] + (size_t)bn * DD;
    const __nv_bfloat16* Bl = g.Blo[z] + (size_t)bn * DD;

    const uint32_t sAh = smem_u32(As_h), sAl = smem_u32(As_l);
    const uint32_t sBh = smem_u32(Bs_h), sBl = smem_u32(Bs_l);

    const int a_row = wm * 64 + (lane & 15);
    const int a_kof = (lane >> 4) << 3;
    const int b_row = wn * 32 + (lane & 7);
    const int b_kof = (lane & 8) ? 8 : 0;

    for (int k0 = 0; k0 < DD; k0 += 32) {
#pragma unroll
        for (int s = 0; s < 2; ++s) {
            int u = tid + s * 256;
            int r = u >> 2, seg = (u & 3) << 3;
            size_t go = (size_t)r * DD + k0 + seg;
            uint32_t so = (uint32_t)(r * SPAD + seg);
            *(uint4*)(As_h + so) = *(const uint4*)(Ah + go);
            *(uint4*)(As_l + so) = *(const uint4*)(Al + go);
            if (r < ncols) {
                *(uint4*)(Bs_h + so) = *(const uint4*)(Bh + go);
                *(uint4*)(Bs_l + so) = *(const uint4*)(Bl + go);
            }
        }
        __syncthreads();
        if (active) {
#pragma unroll
            for (int kk = 0; kk < 32; kk += 16) {
                uint32_t ah[4][4], al[4][4], bh[4][2], bl[4][2];
#pragma unroll
                for (int mt = 0; mt < 4; ++mt) {
                    uint32_t off = (uint32_t)(((a_row + mt * 16) * SPAD + kk + a_kof) * 2);
                    ldsm_x4(ah[mt], sAh + off);
                    ldsm_x4(al[mt], sAl + off);
                }
#pragma unroll
                for (int nt = 0; nt < 4; ++nt) {
                    uint32_t off = (uint32_t)(((b_row + nt * 8) * SPAD + kk + b_kof) * 2);
                    ldsm_x2(bh[nt], sBh + off);
                    ldsm_x2(bl[nt], sBl + off);
                }
#pragma unroll
                for (int mt = 0; mt < 4; ++mt)
#pragma unroll
                    for (int nt = 0; nt < 4; ++nt) {
                        mma16816(acc[mt][nt], ah[mt], bh[nt]);
                        mma16816(acc[mt][nt], ah[mt], bl[nt]);
                        mma16816(acc[mt][nt], al[mt], bh[nt]);
                    }
            }
        }
        __syncthreads();
    }

    float* Cz = g.C[z];
#pragma unroll
    for (int mt = 0; mt < 4; ++mt) {
        int row0 = bm + wm * 64 + mt * 16 + (lane >> 2);
#pragma unroll
        for (int nt = 0; nt < 4; ++nt) {
            int col = bn + wn * 32 + nt * 8 + (lane & 3) * 2;
            if (col < Nz) {
                *(float2*)(Cz + (size_t)row0 * Nz + col) =
                    make_float2(acc[mt][nt][0], acc[mt][nt][1]);
                *(float2*)(Cz + (size_t)(row0 + 8) * Nz + col) =
                    make_float2(acc[mt][nt][2], acc[mt][nt][3]);
            }
        }
    }
}

// ---------------- k_compress ------------------------------------------------
__global__ void compress_kernel(const float* __restrict__ K, float* __restrict__ KC)
{
    int idx = blockIdx.x * blockDim.x + threadIdx.x;
    if (idx >= GG * DD) return;
    int g = idx >> 10;
    int d = idx & 1023;
    float s = 0.f;
#pragma unroll 8
    for (int c = 0; c < CC; ++c)
        s += K[(size_t)(g * CC + c) * DD + d];
    KC[idx] = s * (1.0f / 64.0f);
}

// ---------------- MMA-based fused sparse attention ---------------------------
// grid (16,16), 256 threads. Warps 0-3 = consumers (16 query rows each, flash
// online softmax in registers). Warps 4-7 = producers (double-buffer K/V tiles
// with fp32->bf16 hi/lo split; V stored transposed). Intra (causal) processed
// first (its gated result stashed in smem), then the selected inter blocks.
#define QPAD 72          // bf16 stride for 64-wide tiles
#define TILEB (64 * QPAD * 2)   // 9216 bytes per bf16 tile
// smem byte offsets
#define SQH    0
#define SQL    (SQH + TILEB)
#define SBUF   (SQL + TILEB)              // 2 bufs x 4 tiles (Kh,Kl,Vh,Vl)
#define SKC    (SBUF + 8 * TILEB)         // float [16*65]
#define SSTASH (SKC + 16 * 65 * 4)        // float [64*65]
#define SSC    (SSTASH + 64 * 65 * 4)     // float [8*16]
#define SSELB  (SSC + 512)                // uint  [64]
#define SLIST  (SSELB + 256)              // int   [17]
#define SCNT   (SLIST + 68)               // int
#define SNMASK (SCNT + 4)                 // int
#define ATTN_SMEM (SNMASK + 16)

__global__ void __launch_bounds__(256) attn_mma(
    const float* __restrict__ Qg, const float* __restrict__ Kg,
    const float* __restrict__ Vg, const float* __restrict__ KC,
    const float* __restrict__ GL, float* __restrict__ O)
{
    extern __shared__ char smc[];
    const uint32_t sb = smem_u32(smc);
    __nv_bfloat16* qh = (__nv_bfloat16*)(smc + SQH);
    __nv_bfloat16* ql = (__nv_bfloat16*)(smc + SQL);
    float* kc_s   = (float*)(smc + SKC);
    float* stash  = (float*)(smc + SSTASH);
    float* sc_s   = (float*)(smc + SSC);
    uint32_t* selb = (uint32_t*)(smc + SSELB);
    int* list_s   = (int*)(smc + SLIST);
    int* cnt_s    = (int*)(smc + SCNT);
    int* nmask    = (int*)(smc + SNMASK);

    const int g = blockIdx.x;
    const int h = blockIdx.y;
    const int tid = threadIdx.x;
    const int wid = tid >> 5;
    const int lane = tid & 31;
    const float scale = 0.125f;

    if (tid == 0) *nmask = 0;

    // ---- stage Q (bf16 hi/lo) and compressed keys (fp32) ----
    for (int u = tid; u < 1024; u += 256) {
        int r = u >> 4, seg = (u & 15) << 2;
        float4 qv = *(const float4*)(Qg + (size_t)(g * 64 + r) * DD + h * 64 + seg);
        __nv_bfloat16 a0 = __float2bfloat16_rn(qv.x), a1 = __float2bfloat16_rn(qv.y);
        __nv_bfloat16 a2 = __float2bfloat16_rn(qv.z), a3 = __float2bfloat16_rn(qv.w);
        uint2 hp, lp;
        hp.x = (uint32_t)__bfloat16_as_ushort(a0) | ((uint32_t)__bfloat16_as_ushort(a1) << 16);
        hp.y = (uint32_t)__bfloat16_as_ushort(a2) | ((uint32_t)__bfloat16_as_ushort(a3) << 16);
        lp.x = (uint32_t)__bfloat16_as_ushort(__float2bfloat16_rn(qv.x - __bfloat162float(a0))) |
               ((uint32_t)__bfloat16_as_ushort(__float2bfloat16_rn(qv.y - __bfloat162float(a1))) << 16);
        lp.y = (uint32_t)__bfloat16_as_ushort(__float2bfloat16_rn(qv.z - __bfloat162float(a2))) |
               ((uint32_t)__bfloat16_as_ushort(__float2bfloat16_rn(qv.w - __bfloat162float(a3))) << 16);
        *(uint2*)(qh + r * QPAD + seg) = hp;
        *(uint2*)(ql + r * QPAD + seg) = lp;
    }
    for (int u = tid; u < 1024; u += 256) {
        int gp = u >> 6, d = u & 63;
        kc_s[gp * 65 + d] = KC[(size_t)gp * DD + h * 64 + d];
    }
    __syncthreads();

    // ---- selection (fp32, identical semantics to passing R5 kernel) ----
    for (int qq = 0; qq < 8; ++qq) {
        int qi = wid * 8 + qq;
        int gp = lane & 15;
        int half = lane >> 4;
        float part = 0.f;
#pragma unroll
        for (int d = 0; d < 32; ++d) {
            int di = half * 32 + d;
            float qv = __bfloat162float(qh[qi * QPAD + di]) +
                       __bfloat162float(ql[qi * QPAD + di]);
            part = fmaf(qv, kc_s[gp * 65 + di], part);
        }
        part += __shfl_xor_sync(0xffffffffu, part, 16);
        if (lane < 16) sc_s[wid * 16 + lane] = part;
        __syncwarp();
        float m1 = -INFINITY; int i1 = 0;
#pragma unroll
        for (int gp2 = 0; gp2 < 16; ++gp2) {
            float v = (gp2 > g) ? sc_s[wid * 16 + gp2] : -INFINITY;
            if (v > m1) { m1 = v; i1 = gp2; }
        }
        float m2 = -INFINITY; int i2 = (i1 == 0) ? 1 : 0;
#pragma unroll
        for (int gp2 = 0; gp2 < 16; ++gp2) {
            if (gp2 == i1) continue;
            float v = (gp2 > g) ? sc_s[wid * 16 + gp2] : -INFINITY;
            if (v > m2) { m2 = v; i2 = gp2; }
        }
        if (lane == 0) {
            selb[qi] = (1u << i1) | (1u << i2);
            atomicOr(nmask, (1 << i1) | (1 << i2));
        }
        __syncwarp();
    }
    __syncthreads();

    if (tid == 0) {
        int cnt = 0;
        list_s[cnt++] = g;                       // intra first
        int nm = *nmask;
        for (int jb = 0; jb < 16; ++jb)
            if (nm & (1 << jb)) list_s[cnt++] = jb;
        cnt_s[0] = cnt;
    }
    __syncthreads();
    const int ntot = cnt_s[0];

    // ---- producers stage list[0] into buffer 0 ----
    if (wid >= 4) {
        int pt = tid - 128;
        int jb = list_s[0];
        __nv_bfloat16* kh  = (__nv_bfloat16*)(smc + SBUF);
        __nv_bfloat16* kl  = kh + 64 * QPAD;
        __nv_bfloat16* vth = kl + 64 * QPAD;
        __nv_bfloat16* vtl = vth + 64 * QPAD;
        for (int u = pt; u < 1024; u += 128) {
            int c = u >> 4, seg = (u & 15) << 2;
            size_t go = (size_t)(jb * 64 + c) * DD + h * 64 + seg;
            float4 kv = *(const float4*)(Kg + go);
            __nv_bfloat16 k0 = __float2bfloat16_rn(kv.x), k1 = __float2bfloat16_rn(kv.y);
            __nv_bfloat16 k2 = __float2bfloat16_rn(kv.z), k3 = __float2bfloat16_rn(kv.w);
            uint2 hp, lp;
            hp.x = (uint32_t)__bfloat16_as_ushort(k0) | ((uint32_t)__bfloat16_as_ushort(k1) << 16);
            hp.y = (uint32_t)__bfloat16_as_ushort(k2) | ((uint32_t)__bfloat16_as_ushort(k3) << 16);
            lp.x = (uint32_t)__bfloat16_as_ushort(__float2bfloat16_rn(kv.x - __bfloat162float(k0))) |
                   ((uint32_t)__bfloat16_as_ushort(__float2bfloat16_rn(kv.y - __bfloat162float(k1))) << 16);
            lp.y = (uint32_t)__bfloat16_as_ushort(__float2bfloat16_rn(kv.z - __bfloat162float(k2))) |
                   ((uint32_t)__bfloat16_as_ushort(__float2bfloat16_rn(kv.w - __bfloat162float(k3))) << 16);
            *(uint2*)(kh + c * QPAD + seg) = hp;
            *(uint2*)(kl + c * QPAD + seg) = lp;
            float4 vv = *(const float4*)(Vg + go);
            float vf[4] = {vv.x, vv.y, vv.z, vv.w};
#pragma unroll
            for (int j = 0; j < 4; ++j) {
                __nv_bfloat16 vh = __float2bfloat16_rn(vf[j]);
                vth[(seg + j) * QPAD + c] = vh;
                vtl[(seg + j) * QPAD + c] = __float2bfloat16_rn(vf[j] - __bfloat162float(vh));
            }
        }
    }
    __syncthreads();

    // ---- main pipeline ----
    const int r0 = (wid & 3) * 16 + (lane >> 2);
    const int r1 = r0 + 8;
    const int q2 = (lane & 3) * 2;
    const int akof = (lane >> 4) << 3;
    const int arow = (wid & 3) * 16 + (lane & 15);
    const int brow = lane & 7;
    const int bkof = (lane & 8) ? 8 : 0;

    float m0 = -INFINITY, m1 = -INFINITY, l0 = 0.f, l1 = 0.f;
    float o[8][4];
#pragma unroll
    for (int nt = 0; nt < 8; ++nt)
#pragma unroll
        for (int e = 0; e < 4; ++e) o[nt][e] = 0.f;

    for (int i = 0; i < ntot; ++i) {
        if (wid >= 4) {
            if (i + 1 < ntot) {
                int pt = tid - 128;
                int jb = list_s[i + 1];
                char* bp = smc + SBUF + ((i + 1) & 1) * 4 * TILEB;
                __nv_bfloat16* kh  = (__nv_bfloat16*)bp;
                __nv_bfloat16* kl  = kh + 64 * QPAD;
                __nv_bfloat16* vth = kl + 64 * QPAD;
                __nv_bfloat16* vtl = vth + 64 * QPAD;
                for (int u = pt; u < 1024; u += 128) {
                    int c = u >> 4, seg = (u & 15) << 2;
                    size_t go = (size_t)(jb * 64 + c) * DD + h * 64 + seg;
                    float4 kv = *(const float4*)(Kg + go);
                    __nv_bfloat16 k0 = __float2bfloat16_rn(kv.x), k1 = __float2bfloat16_rn(kv.y);
                    __nv_bfloat16 k2 = __float2bfloat16_rn(kv.z), k3 = __float2bfloat16_rn(kv.w);
                    uint2 hp, lp;
                    hp.x = (uint32_t)__bfloat16_as_ushort(k0) | ((uint32_t)__bfloat16_as_ushort(k1) << 16);
                    hp.y = (uint32_t)__bfloat16_as_ushort(k2) | ((uint32_t)__bfloat16_as_ushort(k3) << 16);
                    lp.x = (uint32_t)__bfloat16_as_ushort(__float2bfloat16_rn(kv.x - __bfloat162float(k0))) |
                           ((uint32_t)__bfloat16_as_ushort(__float2bfloat16_rn(kv.y - __bfloat162float(k1))) << 16);
                    lp.y = (uint32_t)__bfloat16_as_ushort(__float2bfloat16_rn(kv.z - __bfloat162float(k2))) |
                           ((uint32_t)__bfloat16_as_ushort(__float2bfloat16_rn(kv.w - __bfloat162float(k3))) << 16);
                    *(uint2*)(kh + c * QPAD + seg) = hp;
                    *(uint2*)(kl + c * QPAD + seg) = lp;
                    float4 vv = *(const float4*)(Vg + go);
                    float vf[4] = {vv.x, vv.y, vv.z, vv.w};
#pragma unroll
                    for (int j = 0; j < 4; ++j) {
                        __nv_bfloat16 vh = __float2bfloat16_rn(vf[j]);
                        vth[(seg + j) * QPAD + c] = vh;
                        vtl[(seg + j) * QPAD + c] = __float2bfloat16_rn(vf[j] - __bfloat162float(vh));
                    }
                }
            }
        } else {
            const int jb = list_s[i];
            const bool intra = (i == 0);
            const uint32_t bK  = sb + SBUF + (uint32_t)((i & 1) * 4 * TILEB);
            const uint32_t bKl = bK + TILEB;
            const uint32_t bVh = bK + 2 * TILEB;
            const uint32_t bVl = bK + 3 * TILEB;
            const uint32_t sQh = sb + SQH, sQl = sb + SQL;

            // --- S = Q K^T (bf16x3) ---
            float s[8][4];
#pragma unroll
            for (int nt = 0; nt < 8; ++nt)
#pragma unroll
                for (int e = 0; e < 4; ++e) s[nt][e] = 0.f;
#pragma unroll
            for (int kt = 0; kt < 4; ++kt) {
                uint32_t ao = (uint32_t)((arow * QPAD + kt * 16 + akof) * 2);
                uint32_t ah[4], al[4];
                ldsm_x4(ah, sQh + ao);
                ldsm_x4(al, sQl + ao);
#pragma unroll
                for (int nt = 0; nt < 8; ++nt) {
                    uint32_t bo = (uint32_t)(((nt * 8 + brow) * QPAD + kt * 16 + bkof) * 2);
                    uint32_t bh[2], bl[2];
                    ldsm_x2(bh, bK + bo);
                    ldsm_x2(bl, bKl + bo);
                    mma16816(s[nt], ah, bh);
                    mma16816(s[nt], ah, bl);
                    mma16816(s[nt], al, bh);
                }
            }
            // --- scale + mask ---
            const uint32_t sb0 = selb[r0], sb1 = selb[r1];
#pragma unroll
            for (int nt = 0; nt < 8; ++nt) {
                int c0 = nt * 8 + q2, c1 = c0 + 1;
                bool v00, v01, v10, v11;
                if (intra) {
                    v00 = c0 <= r0; v01 = c1 <= r0;
                    v10 = c0 <= r1; v11 = c1 <= r1;
                } else {
                    bool a = (sb0 >> jb) & 1, b = (sb1 >> jb) & 1;
                    v00 = a; v01 = a; v10 = b; v11 = b;
                }
                s[nt][0] = v00 ? s[nt][0] * scale : -INFINITY;
                s[nt][1] = v01 ? s[nt][1] * scale : -INFINITY;
                s[nt][2] = v10 ? s[nt][2] * scale : -INFINITY;
                s[nt][3] = v11 ? s[nt][3] * scale : -INFINITY;
            }
            // --- online softmax ---
            float mx0 = -INFINITY, mx1 = -INFINITY;
#pragma unroll
            for (int nt = 0; nt < 8; ++nt) {
                mx0 = fmaxf(mx0, fmaxf(s[nt][0], s[nt][1]));
                mx1 = fmaxf(mx1, fmaxf(s[nt][2], s[nt][3]));
            }
            mx0 = fmaxf(mx0, __shfl_xor_sync(0xffffffffu, mx0, 1));
            mx0 = fmaxf(mx0, __shfl_xor_sync(0xffffffffu, mx0, 2));
            mx1 = fmaxf(mx1, __shfl_xor_sync(0xffffffffu, mx1, 1));
            mx1 = fmaxf(mx1, __shfl_xor_sync(0xffffffffu, mx1, 2));
            float mn0 = fmaxf(m0, mx0), mn1 = fmaxf(m1, mx1);
            float al0 = (mn0 == -INFINITY) ? 0.f : __expf(m0 - mn0);
            float al1 = (mn1 == -INFINITY) ? 0.f : __expf(m1 - mn1);
            float rs0 = 0.f, rs1 = 0.f;
            uint32_t pha[4][4], pla[4][4];
#pragma unroll
            for (int nt = 0; nt < 8; ++nt) {
                float p0 = (mn0 == -INFINITY) ? 0.f : __expf(s[nt][0] - mn0);
                float p1 = (mn0 == -INFINITY) ? 0.f : __expf(s[nt][1] - mn0);
                float p2 = (mn1 == -INFINITY) ? 0.f : __expf(s[nt][2] - mn1);
                float p3 = (mn1 == -INFINITY) ? 0.f : __expf(s[nt][3] - mn1);
                rs0 += p0 + p1;
                rs1 += p2 + p3;
                int kt = nt >> 1, hf = nt & 1;
                __nv_bfloat16 b0 = __float2bfloat16_rn(p0), b1 = __float2bfloat16_rn(p1);
                __nv_bfloat16 b2 = __float2bfloat16_rn(p2), b3 = __float2bfloat16_rn(p3);
                pha[kt][hf * 2 + 0] = (uint32_t)__bfloat16_as_ushort(b0) |
                                      ((uint32_t)__bfloat16_as_ushort(b1) << 16);
                pha[kt][hf * 2 + 1] = (uint32_t)__bfloat16_as_ushort(b2) |
                                      ((uint32_t)__bfloat16_as_ushort(b3) << 16);
                pla[kt][hf * 2 + 0] = packbf(p0 - __bfloat162float(b0), p1 - __bfloat162float(b1));
                pla[kt][hf * 2 + 1] = packbf(p2 - __bfloat162float(b2), p3 - __bfloat162float(b3));
            }
            rs0 += __shfl_xor_sync(0xffffffffu, rs0, 1);
            rs0 += __shfl_xor_sync(0xffffffffu, rs0, 2);
            rs1 += __shfl_xor_sync(0xffffffffu, rs1, 1);
            rs1 += __shfl_xor_sync(0xffffffffu, rs1, 2);
            l0 = l0 * al0 + rs0;
            l1 = l1 * al1 + rs1;
#pragma unroll
            for (int nt = 0; nt < 8; ++nt) {
                o[nt][0] *= al0; o[nt][1] *= al0;
                o[nt][2] *= al1; o[nt][3] *= al1;
            }
            // --- O += P V (bf16x3) ---
#pragma unroll
            for (int kt = 0; kt < 4; ++kt) {
#pragma unroll
                for (int nt = 0; nt < 8; ++nt) {
                    uint32_t bo = (uint32_t)(((nt * 8 + brow) * QPAD + kt * 16 + bkof) * 2);
                    uint32_t bh[2], bl[2];
                    ldsm_x2(bh, bVh + bo);
                    ldsm_x2(bl, bVl + bo);
                    mma16816(o[nt], pha[kt], bh);
                    mma16816(o[nt], pha[kt], bl);
                    mma16816(o[nt], pla[kt], bh);
                }
            }
            m0 = mn0; m1 = mn1;

            if (intra) {
                // finalize intra: stash g1 * o / l, reset state
                int n0 = g * 64 + r0, n1 = g * 64 + r1;
                float ga0 = GL[(size_t)n0 * 32 + 2 * h], gb0 = GL[(size_t)n0 * 32 + 2 * h + 1];
                float ga1 = GL[(size_t)n1 * 32 + 2 * h], gb1 = GL[(size_t)n1 * 32 + 2 * h + 1];
                float mg0 = fmaxf(ga0, gb0), mg1 = fmaxf(ga1, gb1);
                float e00 = __expf(ga0 - mg0), e01 = __expf(gb0 - mg0);
                float e10 = __expf(ga1 - mg1), e11 = __expf(gb1 - mg1);
                float iv0 = (e01 / (e00 + e01)) / l0;
                float iv1 = (e11 / (e10 + e11)) / l1;
#pragma unroll
                for (int nt = 0; nt < 8; ++nt) {
                    int c = nt * 8 + q2;
                    stash[r0 * 65 + c]     = o[nt][0] * iv0;
                    stash[r0 * 65 + c + 1] = o[nt][1] * iv0;
                    stash[r1 * 65 + c]     = o[nt][2] * iv1;
                    stash[r1 * 65 + c + 1] = o[nt][3] * iv1;
                }
                m0 = -INFINITY; m1 = -INFINITY; l0 = 0.f; l1 = 0.f;
#pragma unroll
                for (int nt = 0; nt < 8; ++nt)
#pragma unroll
                    for (int e = 0; e < 4; ++e) o[nt][e] = 0.f;
            }
        }
        __syncthreads();
    }

    // ---- epilogue: blend inter + stashed intra, write O ----
    if (wid < 4) {
        int n0 = g * 64 + r0, n1 = g * 64 + r1;
        float ga0 = GL[(size_t)n0 * 32 + 2 * h], gb0 = GL[(size_t)n0 * 32 + 2 * h + 1];
        float ga1 = GL[(size_t)n1 * 32 + 2 * h], gb1 = GL[(size_t)n1 * 32 + 2 * h + 1];
        float mg0 = fmaxf(ga0, gb0), mg1 = fmaxf(ga1, gb1);
        float e00 = __expf(ga0 - mg0), e01 = __expf(gb0 - mg0);
        float e10 = __expf(ga1 - mg1), e11 = __expf(gb1 - mg1);
        float iv0 = (e00 / (e00 + e01)) / l0;
        float iv1 = (e10 / (e10 + e11)) / l1;
#pragma unroll
        for (int nt = 0; nt < 8; ++nt) {
            int c = nt * 8 + q2;
            float v0 = o[nt][0] * iv0 + stash[r0 * 65 + c];
            float v1 = o[nt][1] * iv0 + stash[r0 * 65 + c + 1];
            float v2 = o[nt][2] * iv1 + stash[r1 * 65 + c];
            float v3 = o[nt][3] * iv1 + stash[r1 * 65 + c + 1];
            *(float2*)(O + (size_t)n0 * DD + h * 64 + c) = make_float2(v0, v1);
            *(float2*)(O + (size_t)n1 * DD + h * 64 + c) = make_float2(v2, v3);
        }
    }
}

// ---------------- launch -----------------------------------------------------
extern "C" void kernel_launch(void* const* d_in, const int* in_sizes, int n_in,
                              void* d_out, int out_size)
{
    const float* x  = (const float*)d_in[0];
    const float* Wq = (const float*)d_in[1];
    const float* Wk = (const float*)d_in[2];
    const float* Wv = (const float*)d_in[3];
    const float* Wg = (const float*)d_in[4];
    const float* Wo = (const float*)d_in[5];
    float* out = (float*)d_out;

    float *Q, *K, *V, *GL, *KC, *O;
    cudaGetSymbolAddress((void**)&Q,  d_Q);
    cudaGetSymbolAddress((void**)&K,  d_K);
    cudaGetSymbolAddress((void**)&V,  d_V);
    cudaGetSymbolAddress((void**)&GL, d_GL);
    cudaGetSymbolAddress((void**)&KC, d_KC);
    cudaGetSymbolAddress((void**)&O,  d_O);

    __nv_bfloat16 *xh, *xl, *qh, *ql, *kh, *kl, *vh, *vl, *oh, *ol, *gh, *gl2, *obh, *obl;
    cudaGetSymbolAddress((void**)&xh,  sx_hi);  cudaGetSymbolAddress((void**)&xl,  sx_lo);
    cudaGetSymbolAddress((void**)&qh,  swq_hi); cudaGetSymbolAddress((void**)&ql,  swq_lo);
    cudaGetSymbolAddress((void**)&kh,  swk_hi); cudaGetSymbolAddress((void**)&kl,  swk_lo);
    cudaGetSymbolAddress((void**)&vh,  swv_hi); cudaGetSymbolAddress((void**)&vl,  swv_lo);
    cudaGetSymbolAddress((void**)&oh,  swo_hi); cudaGetSymbolAddress((void**)&ol,  swo_lo);
    cudaGetSymbolAddress((void**)&gh,  swg_hi); cudaGetSymbolAddress((void**)&gl2, swg_lo);
    cudaGetSymbolAddress((void**)&obh, so_hi);  cudaGetSymbolAddress((void**)&obl, so_lo);

    // 1) split-convert x + all weights
    ConvArgs ca;
    ca.src[0] = x;  ca.hi[0] = xh;  ca.lo[0] = xl;  ca.n[0] = NN * DD;
    ca.src[1] = Wq; ca.hi[1] = qh;  ca.lo[1] = ql;  ca.n[1] = DD * DD;
    ca.src[2] = Wk; ca.hi[2] = kh;  ca.lo[2] = kl;  ca.n[2] = DD * DD;
    ca.src[3] = Wv; ca.hi[3] = vh;  ca.lo[3] = vl;  ca.n[3] = DD * DD;
    ca.src[4] = Wg; ca.hi[4] = gh;  ca.lo[4] = gl2; ca.n[4] = 32 * DD;
    ca.src[5] = Wo; ca.hi[5] = oh;  ca.lo[5] = ol;  ca.n[5] = DD * DD;
    convert_kernel<<<dim3(1024, 6), 256>>>(ca);

    // 2) QKV + gate projections
    GemmArgs gq;
    gq.Ahi = xh; gq.Alo = xl;
    gq.Bhi[0] = qh; gq.Blo[0] = ql;  gq.C[0] = Q;  gq.N[0] = DD;
    gq.Bhi[1] = kh; gq.Blo[1] = kl;  gq.C[1] = K;  gq.N[1] = DD;
    gq.Bhi[2] = vh; gq.Blo[2] = vl;  gq.C[2] = V;  gq.N[2] = DD;
    gq.Bhi[3] = gh; gq.Blo[3] = gl2; gq.C[3] = GL; gq.N[3] = 32;
    mma_gemm<<<dim3(8, 8, 4), 256>>>(gq);

    // 3) compressed block keys
    compress_kernel<<<(GG * DD + 255) / 256, 256>>>(K, KC);

    // 4) fused sparse attention (tensor-core flash)
    cudaFuncSetAttribute(attn_mma, cudaFuncAttributeMaxDynamicSharedMemorySize, ATTN_SMEM);
    attn_mma<<<dim3(GG, HH), 256, ATTN_SMEM>>>(Q, K, V, KC, GL, O);

    // 5) split-convert O
    ConvArgs co;
    co.src[0] = O; co.hi[0] = obh; co.lo[0] = obl; co.n[0] = NN * DD;
    for (int i = 1; i < 6; ++i) { co.src[i] = O; co.hi[i] = obh; co.lo[i] = obl; co.n[i] = 0; }
    convert_kernel<<<dim3(1024, 1), 256>>>(co);

    // 6) output projection
    GemmArgs go;
    go.Ahi = obh; go.Alo = obl;
    go.Bhi[0] = oh; go.Blo[0] = ol; go.C[0] = out; go.N[0] = DD;
    for (int i = 1; i < 4; ++i) { go.Bhi[i] = oh; go.Blo[i] = ol; go.C[i] = out; go.N[i] = 0; }
    mma_gemm<<<dim3(8, 8, 1), 256>>>(go);
}

// round 7
// speedup vs baseline: 1.2180x; 1.0028x over previous
#include <cuda_runtime.h>
#include <cuda_bf16.h>
#include <math.h>
#include <stdint.h>

#define NN 1024   // tokens
#define DD 1024   // model dim
#define HH 16     // heads
#define CC 64     // chunk size
#define GG 16     // num chunks

// ---------------- scratch (device globals; no allocation allowed) ----------
__device__ __align__(16) float d_Q[NN * DD];
__device__ __align__(16) float d_K[NN * DD];
__device__ __align__(16) float d_V[NN * DD];
__device__ __align__(16) float d_GL[NN * 32];
__device__ __align__(16) float d_KC[GG * DD];
__device__ __align__(16) float d_O[NN * DD];

__device__ __align__(16) __nv_bfloat16 sx_hi[NN * DD], sx_lo[NN * DD];
__device__ __align__(16) __nv_bfloat16 swq_hi[DD * DD], swq_lo[DD * DD];
__device__ __align__(16) __nv_bfloat16 swk_hi[DD * DD], swk_lo[DD * DD];
__device__ __align__(16) __nv_bfloat16 swv_hi[DD * DD], swv_lo[DD * DD];
__device__ __align__(16) __nv_bfloat16 swo_hi[DD * DD], swo_lo[DD * DD];
__device__ __align__(16) __nv_bfloat16 swg_hi[32 * DD], swg_lo[32 * DD];
__device__ __align__(16) __nv_bfloat16 so_hi[NN * DD], so_lo[NN * DD];

// ---------------- helpers ----------------------------------------------------
__device__ __forceinline__ uint32_t smem_u32(const void* p) {
    uint32_t a;
    asm("{ .reg .u64 t; cvta.to.shared.u64 t, %1; cvt.u32.u64 %0, t; }" : "=r"(a) : "l"(p));
    return a;
}
__device__ __forceinline__ void ldsm_x4(uint32_t* r, uint32_t addr) {
    asm volatile("ldmatrix.sync.aligned.m8n8.x4.shared.b16 {%0,%1,%2,%3}, [%4];"
                 : "=r"(r[0]), "=r"(r[1]), "=r"(r[2]), "=r"(r[3]) : "r"(addr));
}
__device__ __forceinline__ void ldsm_x2(uint32_t* r, uint32_t addr) {
    asm volatile("ldmatrix.sync.aligned.m8n8.x2.shared.b16 {%0,%1}, [%2];"
                 : "=r"(r[0]), "=r"(r[1]) : "r"(addr));
}
__device__ __forceinline__ void mma16816(float* d, const uint32_t* a, const uint32_t* b) {
    asm volatile(
        "mma.sync.aligned.m16n8k16.row.col.f32.bf16.bf16.f32 "
        "{%0,%1,%2,%3}, {%4,%5,%6,%7}, {%8,%9}, {%0,%1,%2,%3};"
        : "+f"(d[0]), "+f"(d[1]), "+f"(d[2]), "+f"(d[3])
        : "r"(a[0]), "r"(a[1]), "r"(a[2]), "r"(a[3]), "r"(b[0]), "r"(b[1]));
}
__device__ __forceinline__ uint32_t packbf(float a, float b) {
    __nv_bfloat162 t;
    t.x = __float2bfloat16_rn(a);
    t.y = __float2bfloat16_rn(b);
    return *(uint32_t*)&t;
}

// ---------------- fp32 -> bf16 hi/lo split conversion -----------------------
struct ConvArgs {
    const float* src[6];
    __nv_bfloat16* hi[6];
    __nv_bfloat16* lo[6];
    int n[6];
};

__global__ void convert_kernel(ConvArgs a) {
    int z = blockIdx.y;
    int i4 = (blockIdx.x * blockDim.x + threadIdx.x) * 4;
    if (i4 >= a.n[z]) return;
    float4 v = *(const float4*)(a.src[z] + i4);
    __nv_bfloat16 h0 = __float2bfloat16_rn(v.x);
    __nv_bfloat16 h1 = __float2bfloat16_rn(v.y);
    __nv_bfloat16 h2 = __float2bfloat16_rn(v.z);
    __nv_bfloat16 h3 = __float2bfloat16_rn(v.w);
    __nv_bfloat16 l0 = __float2bfloat16_rn(v.x - __bfloat162float(h0));
    __nv_bfloat16 l1 = __float2bfloat16_rn(v.y - __bfloat162float(h1));
    __nv_bfloat16 l2 = __float2bfloat16_rn(v.z - __bfloat162float(h2));
    __nv_bfloat16 l3 = __float2bfloat16_rn(v.w - __bfloat162float(h3));
    uint2 hp, lp;
    hp.x = (uint32_t)__bfloat16_as_ushort(h0) | ((uint32_t)__bfloat16_as_ushort(h1) << 16);
    hp.y = (uint32_t)__bfloat16_as_ushort(h2) | ((uint32_t)__bfloat16_as_ushort(h3) << 16);
    lp.x = (uint32_t)__bfloat16_as_ushort(l0) | ((uint32_t)__bfloat16_as_ushort(l1) << 16);
    lp.y = (uint32_t)__bfloat16_as_ushort(l2) | ((uint32_t)__bfloat16_as_ushort(l3) << 16);
    *(uint2*)(a.hi[z] + i4) = hp;
    *(uint2*)(a.lo[z] + i4) = lp;
}

// ---------------- HMMA GEMM: C[M,Nz] = A[M,K] @ B[Nz,K]^T -------------------
struct GemmArgs {
    const __nv_bfloat16* Ahi;
    const __nv_bfloat16* Alo;
    const __nv_bfloat16* Bhi[4];
    const __nv_bfloat16* Blo[4];
    float* C[4];
    int N[4];
};

#define SPAD 40

__global__ void __launch_bounds__(256) mma_gemm(GemmArgs g) {
    const int z = blockIdx.z;
    const int Nz = g.N[z];
    const int bn = blockIdx.x * 128;
    if (bn >= Nz) return;
    const int bm = blockIdx.y * 128;
    const int ncols = (Nz - bn < 128) ? (Nz - bn) : 128;

    __shared__ __nv_bfloat16 As_h[128 * SPAD];
    __shared__ __nv_bfloat16 As_l[128 * SPAD];
    __shared__ __nv_bfloat16 Bs_h[128 * SPAD];
    __shared__ __nv_bfloat16 Bs_l[128 * SPAD];

    const int tid = threadIdx.x;
    const int wid = tid >> 5;
    const int lane = tid & 31;
    const int wm = wid >> 2;
    const int wn = wid & 3;
    const bool active = (wn * 32) < ncols;

    float acc[4][4][4];
#pragma unroll
    for (int mt = 0; mt < 4; ++mt)
#pragma unroll
        for (int nt = 0; nt < 4; ++nt)
#pragma unroll
            for (int e = 0; e < 4; ++e) acc[mt][nt][e] = 0.f;

    const __nv_bfloat16* Ah = g.Ahi + (size_t)bm * DD;
    const __nv_bfloat16* Al = g.Alo + (size_t)bm * DD;
    const __nv_bfloat16* Bh = g.Bhi[z] + (size_t)bn * DD;
    const __nv_bfloat16* Bl = g.Blo[z] + (size_t)bn * DD;

    const uint32_t sAh = smem_u32(As_h), sAl = smem_u32(As_l);
    const uint32_t sBh = smem_u32(Bs_h), sBl = smem_u32(Bs_l);

    const int a_row = wm * 64 + (lane & 15);
    const int a_kof = (lane >> 4) << 3;
    const int b_row = wn * 32 + (lane & 7);
    const int b_kof = (lane & 8) ? 8 : 0;

    for (int k0 = 0; k0 < DD; k0 += 32) {
#pragma unroll
        for (int s = 0; s < 2; ++s) {
            int u = tid + s * 256;
            int r = u >> 2, seg = (u & 3) << 3;
            size_t go = (size_t)r * DD + k0 + seg;
            uint32_t so = (uint32_t)(r * SPAD + seg);
            *(uint4*)(As_h + so) = *(const uint4*)(Ah + go);
            *(uint4*)(As_l + so) = *(const uint4*)(Al + go);
            if (r < ncols) {
                *(uint4*)(Bs_h + so) = *(const uint4*)(Bh + go);
                *(uint4*)(Bs_l + so) = *(const uint4*)(Bl + go);
            }
        }
        __syncthreads();
        if (active) {
#pragma unroll
            for (int kk = 0; kk < 32; kk += 16) {
                uint32_t ah[4][4], al[4][4], bh[4][2], bl[4][2];
#pragma unroll
                for (int mt = 0; mt < 4; ++mt) {
                    uint32_t off = (uint32_t)(((a_row + mt * 16) * SPAD + kk + a_kof) * 2);
                    ldsm_x4(ah[mt], sAh + off);
                    ldsm_x4(al[mt], sAl + off);
                }
#pragma unroll
                for (int nt = 0; nt < 4; ++nt) {
                    uint32_t off = (uint32_t)(((b_row + nt * 8) * SPAD + kk + b_kof) * 2);
                    ldsm_x2(bh[nt], sBh + off);
                    ldsm_x2(bl[nt], sBl + off);
                }
#pragma unroll
                for (int mt = 0; mt < 4; ++mt)
#pragma unroll
                    for (int nt = 0; nt < 4; ++nt) {
                        mma16816(acc[mt][nt], ah[mt], bh[nt]);
                        mma16816(acc[mt][nt], ah[mt], bl[nt]);
                        mma16816(acc[mt][nt], al[mt], bh[nt]);
                    }
            }
        }
        __syncthreads();
    }

    float* Cz = g.C[z];
#pragma unroll
    for (int mt = 0; mt < 4; ++mt) {
        int row0 = bm + wm * 64 + mt * 16 + (lane >> 2);
#pragma unroll
        for (int nt = 0; nt < 4; ++nt) {
            int col = bn + wn * 32 + nt * 8 + (lane & 3) * 2;
            if (col < Nz) {
                *(float2*)(Cz + (size_t)row0 * Nz + col) =
                    make_float2(acc[mt][nt][0], acc[mt][nt][1]);
                *(float2*)(Cz + (size_t)(row0 + 8) * Nz + col) =
                    make_float2(acc[mt][nt][2], acc[mt][nt][3]);
            }
        }
    }
}

// ---------------- k_compress ------------------------------------------------
__global__ void compress_kernel(const float* __restrict__ K, float* __restrict__ KC)
{
    int idx = blockIdx.x * blockDim.x + threadIdx.x;
    if (idx >= GG * DD) return;
    int g = idx >> 10;
    int d = idx & 1023;
    float s = 0.f;
#pragma unroll 8
    for (int c = 0; c < CC; ++c)
        s += K[(size_t)(g * CC + c) * DD + d];
    KC[idx] = s * (1.0f / 64.0f);
}

// ---------------- MMA-based fused sparse attention ---------------------------
// grid (16,16), 256 threads. Warps 0-3 = consumers (16 query rows each, flash
// online softmax in registers). Warps 4-7 = producers (double-buffer K/V tiles
// with fp32->bf16 hi/lo split; V stored transposed). Intra (causal) processed
// first (its gated result stashed in smem), then the selected inter blocks.
#define QPAD 72          // bf16 stride for 64-wide tiles
#define TILEB (64 * QPAD * 2)   // 9216 bytes per bf16 tile
// smem byte offsets
#define SQH    0
#define SQL    (SQH + TILEB)
#define SBUF   (SQL + TILEB)              // 2 bufs x 4 tiles (Kh,Kl,Vh,Vl)
#define SKC    (SBUF + 8 * TILEB)         // float [16*65]
#define SSTASH (SKC + 16 * 65 * 4)        // float [64*65]
#define SSC    (SSTASH + 64 * 65 * 4)     // float [8*16]
#define SSELB  (SSC + 512)                // uint  [64]
#define SLIST  (SSELB + 256)              // int   [17]
#define SCNT   (SLIST + 68)               // int
#define SNMASK (SCNT + 4)                 // int
#define ATTN_SMEM (SNMASK + 16)

__global__ void __launch_bounds__(256) attn_mma(
    const float* __restrict__ Qg, const float* __restrict__ Kg,
    const float* __restrict__ Vg, const float* __restrict__ KC,
    const float* __restrict__ GL, float* __restrict__ O)
{
    extern __shared__ char smc[];
    const uint32_t sb = smem_u32(smc);
    __nv_bfloat16* qh = (__nv_bfloat16*)(smc + SQH);
    __nv_bfloat16* ql = (__nv_bfloat16*)(smc + SQL);
    float* kc_s   = (float*)(smc + SKC);
    float* stash  = (float*)(smc + SSTASH);
    float* sc_s   = (float*)(smc + SSC);
    uint32_t* selb = (uint32_t*)(smc + SSELB);
    int* list_s   = (int*)(smc + SLIST);
    int* cnt_s    = (int*)(smc + SCNT);
    int* nmask    = (int*)(smc + SNMASK);

    const int g = blockIdx.x;
    const int h = blockIdx.y;
    const int tid = threadIdx.x;
    const int wid = tid >> 5;
    const int lane = tid & 31;
    const float scale = 0.125f;

    if (tid == 0) *nmask = 0;

    // ---- stage Q (bf16 hi/lo) and compressed keys (fp32) ----
    for (int u = tid; u < 1024; u += 256) {
        int r = u >> 4, seg = (u & 15) << 2;
        float4 qv = *(const float4*)(Qg + (size_t)(g * 64 + r) * DD + h * 64 + seg);
        __nv_bfloat16 a0 = __float2bfloat16_rn(qv.x), a1 = __float2bfloat16_rn(qv.y);
        __nv_bfloat16 a2 = __float2bfloat16_rn(qv.z), a3 = __float2bfloat16_rn(qv.w);
        uint2 hp, lp;
        hp.x = (uint32_t)__bfloat16_as_ushort(a0) | ((uint32_t)__bfloat16_as_ushort(a1) << 16);
        hp.y = (uint32_t)__bfloat16_as_ushort(a2) | ((uint32_t)__bfloat16_as_ushort(a3) << 16);
        lp.x = (uint32_t)__bfloat16_as_ushort(__float2bfloat16_rn(qv.x - __bfloat162float(a0))) |
               ((uint32_t)__bfloat16_as_ushort(__float2bfloat16_rn(qv.y - __bfloat162float(a1))) << 16);
        lp.y = (uint32_t)__bfloat16_as_ushort(__float2bfloat16_rn(qv.z - __bfloat162float(a2))) |
               ((uint32_t)__bfloat16_as_ushort(__float2bfloat16_rn(qv.w - __bfloat162float(a3))) << 16);
        *(uint2*)(qh + r * QPAD + seg) = hp;
        *(uint2*)(ql + r * QPAD + seg) = lp;
    }
    for (int u = tid; u < 1024; u += 256) {
        int gp = u >> 6, d = u & 63;
        kc_s[gp * 65 + d] = KC[(size_t)gp * DD + h * 64 + d];
    }
    __syncthreads();

    // ---- selection (fp32, identical semantics to passing R5 kernel) ----
    for (int qq = 0; qq < 8; ++qq) {
        int qi = wid * 8 + qq;
        int gp = lane & 15;
        int half = lane >> 4;
        float part = 0.f;
#pragma unroll
        for (int d = 0; d < 32; ++d) {
            int di = half * 32 + d;
            float qv = __bfloat162float(qh[qi * QPAD + di]) +
                       __bfloat162float(ql[qi * QPAD + di]);
            part = fmaf(qv, kc_s[gp * 65 + di], part);
        }
        part += __shfl_xor_sync(0xffffffffu, part, 16);
        if (lane < 16) sc_s[wid * 16 + lane] = part;
        __syncwarp();
        float m1 = -INFINITY; int i1 = 0;
#pragma unroll
        for (int gp2 = 0; gp2 < 16; ++gp2) {
            float v = (gp2 > g) ? sc_s[wid * 16 + gp2] : -INFINITY;
            if (v > m1) { m1 = v; i1 = gp2; }
        }
        float m2 = -INFINITY; int i2 = (i1 == 0) ? 1 : 0;
#pragma unroll
        for (int gp2 = 0; gp2 < 16; ++gp2) {
            if (gp2 == i1) continue;
            float v = (gp2 > g) ? sc_s[wid * 16 + gp2] : -INFINITY;
            if (v > m2) { m2 = v; i2 = gp2; }
        }
        if (lane == 0) {
            selb[qi] = (1u << i1) | (1u << i2);
            atomicOr(nmask, (1 << i1) | (1 << i2));
        }
        __syncwarp();
    }
    __syncthreads();

    if (tid == 0) {
        int cnt = 0;
        list_s[cnt++] = g;                       // intra first
        int nm = *nmask;
        for (int jb = 0; jb < 16; ++jb)
            if (nm & (1 << jb)) list_s[cnt++] = jb;
        cnt_s[0] = cnt;
    }
    __syncthreads();
    const int ntot = cnt_s[0];

    // ---- producers stage list[0] into buffer 0 ----
    if (wid >= 4) {
        int pt = tid - 128;
        int jb = list_s[0];
        __nv_bfloat16* kh  = (__nv_bfloat16*)(smc + SBUF);
        __nv_bfloat16* kl  = kh + 64 * QPAD;
        __nv_bfloat16* vth = kl + 64 * QPAD;
        __nv_bfloat16* vtl = vth + 64 * QPAD;
        for (int u = pt; u < 1024; u += 128) {
            int c = u >> 4, seg = (u & 15) << 2;
            size_t go = (size_t)(jb * 64 + c) * DD + h * 64 + seg;
            float4 kv = *(const float4*)(Kg + go);
            __nv_bfloat16 k0 = __float2bfloat16_rn(kv.x), k1 = __float2bfloat16_rn(kv.y);
            __nv_bfloat16 k2 = __float2bfloat16_rn(kv.z), k3 = __float2bfloat16_rn(kv.w);
            uint2 hp, lp;
            hp.x = (uint32_t)__bfloat16_as_ushort(k0) | ((uint32_t)__bfloat16_as_ushort(k1) << 16);
            hp.y = (uint32_t)__bfloat16_as_ushort(k2) | ((uint32_t)__bfloat16_as_ushort(k3) << 16);
            lp.x = (uint32_t)__bfloat16_as_ushort(__float2bfloat16_rn(kv.x - __bfloat162float(k0))) |
                   ((uint32_t)__bfloat16_as_ushort(__float2bfloat16_rn(kv.y - __bfloat162float(k1))) << 16);
            lp.y = (uint32_t)__bfloat16_as_ushort(__float2bfloat16_rn(kv.z - __bfloat162float(k2))) |
                   ((uint32_t)__bfloat16_as_ushort(__float2bfloat16_rn(kv.w - __bfloat162float(k3))) << 16);
            *(uint2*)(kh + c * QPAD + seg) = hp;
            *(uint2*)(kl + c * QPAD + seg) = lp;
            float4 vv = *(const float4*)(Vg + go);
            float vf[4] = {vv.x, vv.y, vv.z, vv.w};
#pragma unroll
            for (int j = 0; j < 4; ++j) {
                __nv_bfloat16 vh = __float2bfloat16_rn(vf[j]);
                vth[(seg + j) * QPAD + c] = vh;
                vtl[(seg + j) * QPAD + c] = __float2bfloat16_rn(vf[j] - __bfloat162float(vh));
            }
        }
    }
    __syncthreads();

    // ---- main pipeline ----
    const int r0 = (wid & 3) * 16 + (lane >> 2);
    const int r1 = r0 + 8;
    const int q2 = (lane & 3) * 2;
    const int akof = (lane >> 4) << 3;
    const int arow = (wid & 3) * 16 + (lane & 15);
    const int brow = lane & 7;
    const int bkof = (lane & 8) ? 8 : 0;

    float m0 = -INFINITY, m1 = -INFINITY, l0 = 0.f, l1 = 0.f;
    float o[8][4];
#pragma unroll
    for (int nt = 0; nt < 8; ++nt)
#pragma unroll
        for (int e = 0; e < 4; ++e) o[nt][e] = 0.f;

    for (int i = 0; i < ntot; ++i) {
        if (wid >= 4) {
            if (i + 1 < ntot) {
                int pt = tid - 128;
                int jb = list_s[i + 1];
                char* bp = smc + SBUF + ((i + 1) & 1) * 4 * TILEB;
                __nv_bfloat16* kh  = (__nv_bfloat16*)bp;
                __nv_bfloat16* kl  = kh + 64 * QPAD;
                __nv_bfloat16* vth = kl + 64 * QPAD;
                __nv_bfloat16* vtl = vth + 64 * QPAD;
                for (int u = pt; u < 1024; u += 128) {
                    int c = u >> 4, seg = (u & 15) << 2;
                    size_t go = (size_t)(jb * 64 + c) * DD + h * 64 + seg;
                    float4 kv = *(const float4*)(Kg + go);
                    __nv_bfloat16 k0 = __float2bfloat16_rn(kv.x), k1 = __float2bfloat16_rn(kv.y);
                    __nv_bfloat16 k2 = __float2bfloat16_rn(kv.z), k3 = __float2bfloat16_rn(kv.w);
                    uint2 hp, lp;
                    hp.x = (uint32_t)__bfloat16_as_ushort(k0) | ((uint32_t)__bfloat16_as_ushort(k1) << 16);
                    hp.y = (uint32_t)__bfloat16_as_ushort(k2) | ((uint32_t)__bfloat16_as_ushort(k3) << 16);
                    lp.x = (uint32_t)__bfloat16_as_ushort(__float2bfloat16_rn(kv.x - __bfloat162float(k0))) |
                           ((uint32_t)__bfloat16_as_ushort(__float2bfloat16_rn(kv.y - __bfloat162float(k1))) << 16);
                    lp.y = (uint32_t)__bfloat16_as_ushort(__float2bfloat16_rn(kv.z - __bfloat162float(k2))) |
                           ((uint32_t)__bfloat16_as_ushort(__float2bfloat16_rn(kv.w - __bfloat162float(k3))) << 16);
                    *(uint2*)(kh + c * QPAD + seg) = hp;
                    *(uint2*)(kl + c * QPAD + seg) = lp;
                    float4 vv = *(const float4*)(Vg + go);
                    float vf[4] = {vv.x, vv.y, vv.z, vv.w};
#pragma unroll
                    for (int j = 0; j < 4; ++j) {
                        __nv_bfloat16 vh = __float2bfloat16_rn(vf[j]);
                        vth[(seg + j) * QPAD + c] = vh;
                        vtl[(seg + j) * QPAD + c] = __float2bfloat16_rn(vf[j] - __bfloat162float(vh));
                    }
                }
            }
        } else {
            const int jb = list_s[i];
            const bool intra = (i == 0);
            const uint32_t bK  = sb + SBUF + (uint32_t)((i & 1) * 4 * TILEB);
            const uint32_t bKl = bK + TILEB;
            const uint32_t bVh = bK + 2 * TILEB;
            const uint32_t bVl = bK + 3 * TILEB;
            const uint32_t sQh = sb + SQH, sQl = sb + SQL;

            // --- S = Q K^T (bf16x3) ---
            float s[8][4];
#pragma unroll
            for (int nt = 0; nt < 8; ++nt)
#pragma unroll
                for (int e = 0; e < 4; ++e) s[nt][e] = 0.f;
#pragma unroll
            for (int kt = 0; kt < 4; ++kt) {
                uint32_t ao = (uint32_t)((arow * QPAD + kt * 16 + akof) * 2);
                uint32_t ah[4], al[4];
                ldsm_x4(ah, sQh + ao);
                ldsm_x4(al, sQl + ao);
#pragma unroll
                for (int nt = 0; nt < 8; ++nt) {
                    uint32_t bo = (uint32_t)(((nt * 8 + brow) * QPAD + kt * 16 + bkof) * 2);
                    uint32_t bh[2], bl[2];
                    ldsm_x2(bh, bK + bo);
                    ldsm_x2(bl, bKl + bo);
                    mma16816(s[nt], ah, bh);
                    mma16816(s[nt], ah, bl);
                    mma16816(s[nt], al, bh);
                }
            }
            // --- scale + mask ---
            const uint32_t sb0 = selb[r0], sb1 = selb[r1];
#pragma unroll
            for (int nt = 0; nt < 8; ++nt) {
                int c0 = nt * 8 + q2, c1 = c0 + 1;
                bool v00, v01, v10, v11;
                if (intra) {
                    v00 = c0 <= r0; v01 = c1 <= r0;
                    v10 = c0 <= r1; v11 = c1 <= r1;
                } else {
                    bool a = (sb0 >> jb) & 1, b = (sb1 >> jb) & 1;
                    v00 = a; v01 = a; v10 = b; v11 = b;
                }
                s[nt][0] = v00 ? s[nt][0] * scale : -INFINITY;
                s[nt][1] = v01 ? s[nt][1] * scale : -INFINITY;
                s[nt][2] = v10 ? s[nt][2] * scale : -INFINITY;
                s[nt][3] = v11 ? s[nt][3] * scale : -INFINITY;
            }
            // --- online softmax ---
            float mx0 = -INFINITY, mx1 = -INFINITY;
#pragma unroll
            for (int nt = 0; nt < 8; ++nt) {
                mx0 = fmaxf(mx0, fmaxf(s[nt][0], s[nt][1]));
                mx1 = fmaxf(mx1, fmaxf(s[nt][2], s[nt][3]));
            }
            mx0 = fmaxf(mx0, __shfl_xor_sync(0xffffffffu, mx0, 1));
            mx0 = fmaxf(mx0, __shfl_xor_sync(0xffffffffu, mx0, 2));
            mx1 = fmaxf(mx1, __shfl_xor_sync(0xffffffffu, mx1, 1));
            mx1 = fmaxf(mx1, __shfl_xor_sync(0xffffffffu, mx1, 2));
            float mn0 = fmaxf(m0, mx0), mn1 = fmaxf(m1, mx1);
            float al0 = (mn0 == -INFINITY) ? 0.f : __expf(m0 - mn0);
            float al1 = (mn1 == -INFINITY) ? 0.f : __expf(m1 - mn1);
            float rs0 = 0.f, rs1 = 0.f;
            uint32_t pha[4][4], pla[4][4];
#pragma unroll
            for (int nt = 0; nt < 8; ++nt) {
                float p0 = (mn0 == -INFINITY) ? 0.f : __expf(s[nt][0] - mn0);
                float p1 = (mn0 == -INFINITY) ? 0.f : __expf(s[nt][1] - mn0);
                float p2 = (mn1 == -INFINITY) ? 0.f : __expf(s[nt][2] - mn1);
                float p3 = (mn1 == -INFINITY) ? 0.f : __expf(s[nt][3] - mn1);
                rs0 += p0 + p1;
                rs1 += p2 + p3;
                int kt = nt >> 1, hf = nt & 1;
                __nv_bfloat16 b0 = __float2bfloat16_rn(p0), b1 = __float2bfloat16_rn(p1);
                __nv_bfloat16 b2 = __float2bfloat16_rn(p2), b3 = __float2bfloat16_rn(p3);
                pha[kt][hf * 2 + 0] = (uint32_t)__bfloat16_as_ushort(b0) |
                                      ((uint32_t)__bfloat16_as_ushort(b1) << 16);
                pha[kt][hf * 2 + 1] = (uint32_t)__bfloat16_as_ushort(b2) |
                                      ((uint32_t)__bfloat16_as_ushort(b3) << 16);
                pla[kt][hf * 2 + 0] = packbf(p0 - __bfloat162float(b0), p1 - __bfloat162float(b1));
                pla[kt][hf * 2 + 1] = packbf(p2 - __bfloat162float(b2), p3 - __bfloat162float(b3));
            }
            rs0 += __shfl_xor_sync(0xffffffffu, rs0, 1);
            rs0 += __shfl_xor_sync(0xffffffffu, rs0, 2);
            rs1 += __shfl_xor_sync(0xffffffffu, rs1, 1);
            rs1 += __shfl_xor_sync(0xffffffffu, rs1, 2);
            l0 = l0 * al0 + rs0;
            l1 = l1 * al1 + rs1;
#pragma unroll
            for (int nt = 0; nt < 8; ++nt) {
                o[nt][0] *= al0; o[nt][1] *= al0;
                o[nt][2] *= al1; o[nt][3] *= al1;
            }
            // --- O += P V (bf16x3) ---
#pragma unroll
            for (int kt = 0; kt < 4; ++kt) {
#pragma unroll
                for (int nt = 0; nt < 8; ++nt) {
                    uint32_t bo = (uint32_t)(((nt * 8 + brow) * QPAD + kt * 16 + bkof) * 2);
                    uint32_t bh[2], bl[2];
                    ldsm_x2(bh, bVh + bo);
                    ldsm_x2(bl, bVl + bo);
                    mma16816(o[nt], pha[kt], bh);
                    mma16816(o[nt], pha[kt], bl);
                    mma16816(o[nt], pla[kt], bh);
                }
            }
            m0 = mn0; m1 = mn1;

            if (intra) {
                // finalize intra: stash g1 * o / l, reset state
                int n0 = g * 64 + r0, n1 = g * 64 + r1;
                float ga0 = GL[(size_t)n0 * 32 + 2 * h], gb0 = GL[(size_t)n0 * 32 + 2 * h + 1];
                float ga1 = GL[(size_t)n1 * 32 + 2 * h], gb1 = GL[(size_t)n1 * 32 + 2 * h + 1];
                float mg0 = fmaxf(ga0, gb0), mg1 = fmaxf(ga1, gb1);
                float e00 = __expf(ga0 - mg0), e01 = __expf(gb0 - mg0);
                float e10 = __expf(ga1 - mg1), e11 = __expf(gb1 - mg1);
                float iv0 = (e01 / (e00 + e01)) / l0;
                float iv1 = (e11 / (e10 + e11)) / l1;
#pragma unroll
                for (int nt = 0; nt < 8; ++nt) {
                    int c = nt * 8 + q2;
                    stash[r0 * 65 + c]     = o[nt][0] * iv0;
                    stash[r0 * 65 + c + 1] = o[nt][1] * iv0;
                    stash[r1 * 65 + c]     = o[nt][2] * iv1;
                    stash[r1 * 65 + c + 1] = o[nt][3] * iv1;
                }
                m0 = -INFINITY; m1 = -INFINITY; l0 = 0.f; l1 = 0.f;
#pragma unroll
                for (int nt = 0; nt < 8; ++nt)
#pragma unroll
                    for (int e = 0; e < 4; ++e) o[nt][e] = 0.f;
            }
        }
        __syncthreads();
    }

    // ---- epilogue: blend inter + stashed intra, write O ----
    if (wid < 4) {
        int n0 = g * 64 + r0, n1 = g * 64 + r1;
        float ga0 = GL[(size_t)n0 * 32 + 2 * h], gb0 = GL[(size_t)n0 * 32 + 2 * h + 1];
        float ga1 = GL[(size_t)n1 * 32 + 2 * h], gb1 = GL[(size_t)n1 * 32 + 2 * h + 1];
        float mg0 = fmaxf(ga0, gb0), mg1 = fmaxf(ga1, gb1);
        float e00 = __expf(ga0 - mg0), e01 = __expf(gb0 - mg0);
        float e10 = __expf(ga1 - mg1), e11 = __expf(gb1 - mg1);
        float iv0 = (e00 / (e00 + e01)) / l0;
        float iv1 = (e10 / (e10 + e11)) / l1;
#pragma unroll
        for (int nt = 0; nt < 8; ++nt) {
            int c = nt * 8 + q2;
            float v0 = o[nt][0] * iv0 + stash[r0 * 65 + c];
            float v1 = o[nt][1] * iv0 + stash[r0 * 65 + c + 1];
            float v2 = o[nt][2] * iv1 + stash[r1 * 65 + c];
            float v3 = o[nt][3] * iv1 + stash[r1 * 65 + c + 1];
            *(float2*)(O + (size_t)n0 * DD + h * 64 + c) = make_float2(v0, v1);
            *(float2*)(O + (size_t)n1 * DD + h * 64 + c) = make_float2(v2, v3);
        }
    }
}

// ---------------- launch -----------------------------------------------------
extern "C" void kernel_launch(void* const* d_in, const int* in_sizes, int n_in,
                              void* d_out, int out_size)
{
    const float* x  = (const float*)d_in[0];
    const float* Wq = (const float*)d_in[1];
    const float* Wk = (const float*)d_in[2];
    const float* Wv = (const float*)d_in[3];
    const float* Wg = (const float*)d_in[4];
    const float* Wo = (const float*)d_in[5];
    float* out = (float*)d_out;

    float *Q, *K, *V, *GL, *KC, *O;
    cudaGetSymbolAddress((void**)&Q,  d_Q);
    cudaGetSymbolAddress((void**)&K,  d_K);
    cudaGetSymbolAddress((void**)&V,  d_V);
    cudaGetSymbolAddress((void**)&GL, d_GL);
    cudaGetSymbolAddress((void**)&KC, d_KC);
    cudaGetSymbolAddress((void**)&O,  d_O);

    __nv_bfloat16 *xh, *xl, *qh, *ql, *kh, *kl, *vh, *vl, *oh, *ol, *gh, *gl2, *obh, *obl;
    cudaGetSymbolAddress((void**)&xh,  sx_hi);  cudaGetSymbolAddress((void**)&xl,  sx_lo);
    cudaGetSymbolAddress((void**)&qh,  swq_hi); cudaGetSymbolAddress((void**)&ql,  swq_lo);
    cudaGetSymbolAddress((void**)&kh,  swk_hi); cudaGetSymbolAddress((void**)&kl,  swk_lo);
    cudaGetSymbolAddress((void**)&vh,  swv_hi); cudaGetSymbolAddress((void**)&vl,  swv_lo);
    cudaGetSymbolAddress((void**)&oh,  swo_hi); cudaGetSymbolAddress((void**)&ol,  swo_lo);
    cudaGetSymbolAddress((void**)&gh,  swg_hi); cudaGetSymbolAddress((void**)&gl2, swg_lo);
    cudaGetSymbolAddress((void**)&obh, so_hi);  cudaGetSymbolAddress((void**)&obl, so_lo);

    // 1) split-convert x + all weights
    ConvArgs ca;
    ca.src[0] = x;  ca.hi[0] = xh;  ca.lo[0] = xl;  ca.n[0] = NN * DD;
    ca.src[1] = Wq; ca.hi[1] = qh;  ca.lo[1] = ql;  ca.n[1] = DD * DD;
    ca.src[2] = Wk; ca.hi[2] = kh;  ca.lo[2] = kl;  ca.n[2] = DD * DD;
    ca.src[3] = Wv; ca.hi[3] = vh;  ca.lo[3] = vl;  ca.n[3] = DD * DD;
    ca.src[4] = Wg; ca.hi[4] = gh;  ca.lo[4] = gl2; ca.n[4] = 32 * DD;
    ca.src[5] = Wo; ca.hi[5] = oh;  ca.lo[5] = ol;  ca.n[5] = DD * DD;
    convert_kernel<<<dim3(1024, 6), 256>>>(ca);

    // 2) QKV + gate projections
    GemmArgs gq;
    gq.Ahi = xh; gq.Alo = xl;
    gq.Bhi[0] = qh; gq.Blo[0] = ql;  gq.C[0] = Q;  gq.N[0] = DD;
    gq.Bhi[1] = kh; gq.Blo[1] = kl;  gq.C[1] = K;  gq.N[1] = DD;
    gq.Bhi[2] = vh; gq.Blo[2] = vl;  gq.C[2] = V;  gq.N[2] = DD;
    gq.Bhi[3] = gh; gq.Blo[3] = gl2; gq.C[3] = GL; gq.N[3] = 32;
    mma_gemm<<<dim3(8, 8, 4), 256>>>(gq);

    // 3) compressed block keys
    compress_kernel<<<(GG * DD + 255) / 256, 256>>>(K, KC);

    // 4) fused sparse attention (tensor-core flash)
    cudaFuncSetAttribute(attn_mma, cudaFuncAttributeMaxDynamicSharedMemorySize, ATTN_SMEM);
    attn_mma<<<dim3(GG, HH), 256, ATTN_SMEM>>>(Q, K, V, KC, GL, O);

    // 5) split-convert O
    ConvArgs co;
    co.src[0] = O; co.hi[0] = obh; co.lo[0] = obl; co.n[0] = NN * DD;
    for (int i = 1; i < 6; ++i) { co.src[i] = O; co.hi[i] = obh; co.lo[i] = obl; co.n[i] = 0; }
    convert_kernel<<<dim3(1024, 1), 256>>>(co);

    // 6) output projection
    GemmArgs go;
    go.Ahi = obh; go.Alo = obl;
    go.Bhi[0] = oh; go.Blo[0] = ol; go.C[0] = out; go.N[0] = DD;
    for (int i = 1; i < 4; ++i) { go.Bhi[i] = oh; go.Blo[i] = ol; go.C[i] = out; go.N[i] = 0; }
    mma_gemm<<<dim3(8, 8, 1), 256>>>(go);
}

// round 8
// speedup vs baseline: 1.2205x; 1.0021x over previous
#include <cuda_runtime.h>
#include <cuda_bf16.h>
#include <math.h>
#include <stdint.h>

#define NN 1024   // tokens
#define DD 1024   // model dim
#define HH 16     // heads
#define CC 64     // chunk size
#define GG 16     // num chunks

// ---------------- scratch (device globals; no allocation allowed) ----------
__device__ __align__(16) float d_Q[NN * DD];
__device__ __align__(16) float d_K[NN * DD];
__device__ __align__(16) float d_V[NN * DD];
__device__ __align__(16) float d_GL[NN * 32];
__device__ __align__(16) float d_KC[GG * DD];
__device__ __align__(16) float d_O[NN * DD];

__device__ __align__(16) __nv_bfloat16 sx_hi[NN * DD], sx_lo[NN * DD];
__device__ __align__(16) __nv_bfloat16 swq_hi[DD * DD], swq_lo[DD * DD];
__device__ __align__(16) __nv_bfloat16 swk_hi[DD * DD], swk_lo[DD * DD];
__device__ __align__(16) __nv_bfloat16 swv_hi[DD * DD], swv_lo[DD * DD];
__device__ __align__(16) __nv_bfloat16 swo_hi[DD * DD], swo_lo[DD * DD];
__device__ __align__(16) __nv_bfloat16 swg_hi[32 * DD], swg_lo[32 * DD];
__device__ __align__(16) __nv_bfloat16 so_hi[NN * DD], so_lo[NN * DD];

// ---------------- helpers ----------------------------------------------------
__device__ __forceinline__ uint32_t smem_u32(const void* p) {
    uint32_t a;
    asm("{ .reg .u64 t; cvta.to.shared.u64 t, %1; cvt.u32.u64 %0, t; }" : "=r"(a) : "l"(p));
    return a;
}
__device__ __forceinline__ void ldsm_x4(uint32_t* r, uint32_t addr) {
    asm volatile("ldmatrix.sync.aligned.m8n8.x4.shared.b16 {%0,%1,%2,%3}, [%4];"
                 : "=r"(r[0]), "=r"(r[1]), "=r"(r[2]), "=r"(r[3]) : "r"(addr));
}
__device__ __forceinline__ void ldsm_x2(uint32_t* r, uint32_t addr) {
    asm volatile("ldmatrix.sync.aligned.m8n8.x2.shared.b16 {%0,%1}, [%2];"
                 : "=r"(r[0]), "=r"(r[1]) : "r"(addr));
}
__device__ __forceinline__ void mma16816(float* d, const uint32_t* a, const uint32_t* b) {
    asm volatile(
        "mma.sync.aligned.m16n8k16.row.col.f32.bf16.bf16.f32 "
        "{%0,%1,%2,%3}, {%4,%5,%6,%7}, {%8,%9}, {%0,%1,%2,%3};"
        : "+f"(d[0]), "+f"(d[1]), "+f"(d[2]), "+f"(d[3])
        : "r"(a[0]), "r"(a[1]), "r"(a[2]), "r"(a[3]), "r"(b[0]), "r"(b[1]));
}
__device__ __forceinline__ uint32_t packbf(float a, float b) {
    __nv_bfloat162 t;
    t.x = __float2bfloat16_rn(a);
    t.y = __float2bfloat16_rn(b);
    return *(uint32_t*)&t;
}

// ---------------- fp32 -> bf16 hi/lo split conversion -----------------------
struct ConvArgs {
    const float* src[6];
    __nv_bfloat16* hi[6];
    __nv_bfloat16* lo[6];
    int n[6];
};

__global__ void convert_kernel(ConvArgs a) {
    int z = blockIdx.y;
    int i4 = (blockIdx.x * blockDim.x + threadIdx.x) * 4;
    if (i4 >= a.n[z]) return;
    float4 v = *(const float4*)(a.src[z] + i4);
    __nv_bfloat16 h0 = __float2bfloat16_rn(v.x);
    __nv_bfloat16 h1 = __float2bfloat16_rn(v.y);
    __nv_bfloat16 h2 = __float2bfloat16_rn(v.z);
    __nv_bfloat16 h3 = __float2bfloat16_rn(v.w);
    __nv_bfloat16 l0 = __float2bfloat16_rn(v.x - __bfloat162float(h0));
    __nv_bfloat16 l1 = __float2bfloat16_rn(v.y - __bfloat162float(h1));
    __nv_bfloat16 l2 = __float2bfloat16_rn(v.z - __bfloat162float(h2));
    __nv_bfloat16 l3 = __float2bfloat16_rn(v.w - __bfloat162float(h3));
    uint2 hp, lp;
    hp.x = (uint32_t)__bfloat16_as_ushort(h0) | ((uint32_t)__bfloat16_as_ushort(h1) << 16);
    hp.y = (uint32_t)__bfloat16_as_ushort(h2) | ((uint32_t)__bfloat16_as_ushort(h3) << 16);
    lp.x = (uint32_t)__bfloat16_as_ushort(l0) | ((uint32_t)__bfloat16_as_ushort(l1) << 16);
    lp.y = (uint32_t)__bfloat16_as_ushort(l2) | ((uint32_t)__bfloat16_as_ushort(l3) << 16);
    *(uint2*)(a.hi[z] + i4) = hp;
    *(uint2*)(a.lo[z] + i4) = lp;
}

// ---------------- HMMA GEMM: C[M,Nz] = A[M,K] @ B[Nz,K]^T -------------------
struct GemmArgs {
    const __nv_bfloat16* Ahi;
    const __nv_bfloat16* Alo;
    const __nv_bfloat16* Bhi[4];
    const __nv_bfloat16* Blo[4];
    float* C[4];
    int N[4];
};

#define SPAD 40

__global__ void __launch_bounds__(256) mma_gemm(GemmArgs g) {
    const int z = blockIdx.z;
    const int Nz = g.N[z];
    const int bn = blockIdx.x * 128;
    if (bn >= Nz) return;
    const int bm = blockIdx.y * 128;
    const int ncols = (Nz - bn < 128) ? (Nz - bn) : 128;

    __shared__ __nv_bfloat16 As_h[128 * SPAD];
    __shared__ __nv_bfloat16 As_l[128 * SPAD];
    __shared__ __nv_bfloat16 Bs_h[128 * SPAD];
    __shared__ __nv_bfloat16 Bs_l[128 * SPAD];

    const int tid = threadIdx.x;
    const int wid = tid >> 5;
    const int lane = tid & 31;
    const int wm = wid >> 2;
    const int wn = wid & 3;
    const bool active = (wn * 32) < ncols;

    float acc[4][4][4];
#pragma unroll
    for (int mt = 0; mt < 4; ++mt)
#pragma unroll
        for (int nt = 0; nt < 4; ++nt)
#pragma unroll
            for (int e = 0; e < 4; ++e) acc[mt][nt][e] = 0.f;

    const __nv_bfloat16* Ah = g.Ahi + (size_t)bm * DD;
    const __nv_bfloat16* Al = g.Alo + (size_t)bm * DD;
    const __nv_bfloat16* Bh = g.Bhi[z] + (size_t)bn * DD;
    const __nv_bfloat16* Bl = g.Blo[z] + (size_t)bn * DD;

    const uint32_t sAh = smem_u32(As_h), sAl = smem_u32(As_l);
    const uint32_t sBh = smem_u32(Bs_h), sBl = smem_u32(Bs_l);

    const int a_row = wm * 64 + (lane & 15);
    const int a_kof = (lane >> 4) << 3;
    const int b_row = wn * 32 + (lane & 7);
    const int b_kof = (lane & 8) ? 8 : 0;

    for (int k0 = 0; k0 < DD; k0 += 32) {
#pragma unroll
        for (int s = 0; s < 2; ++s) {
            int u = tid + s * 256;
            int r = u >> 2, seg = (u & 3) << 3;
            size_t go = (size_t)r * DD + k0 + seg;
            uint32_t so = (uint32_t)(r * SPAD + seg);
            *(uint4*)(As_h + so) = *(const uint4*)(Ah + go);
            *(uint4*)(As_l + so) = *(const uint4*)(Al + go);
            if (r < ncols) {
                *(uint4*)(Bs_h + so) = *(const uint4*)(Bh + go);
                *(uint4*)(Bs_l + so) = *(const uint4*)(Bl + go);
            }
        }
        __syncthreads();
        if (active) {
#pragma unroll
            for (int kk = 0; kk < 32; kk += 16) {
                uint32_t ah[4][4], al[4][4], bh[4][2], bl[4][2];
#pragma unroll
                for (int mt = 0; mt < 4; ++mt) {
                    uint32_t off = (uint32_t)(((a_row + mt * 16) * SPAD + kk + a_kof) * 2);
                    ldsm_x4(ah[mt], sAh + off);
                    ldsm_x4(al[mt], sAl + off);
                }
#pragma unroll
                for (int nt = 0; nt < 4; ++nt) {
                    uint32_t off = (uint32_t)(((b_row + nt * 8) * SPAD + kk + b_kof) * 2);
                    ldsm_x2(bh[nt], sBh + off);
                    ldsm_x2(bl[nt], sBl + off);
                }
#pragma unroll
                for (int mt = 0; mt < 4; ++mt)
#pragma unroll
                    for (int nt = 0; nt < 4; ++nt) {
                        mma16816(acc[mt][nt], ah[mt], bh[nt]);
                        mma16816(acc[mt][nt], ah[mt], bl[nt]);
                        mma16816(acc[mt][nt], al[mt], bh[nt]);
                    }
            }
        }
        __syncthreads();
    }

    float* Cz = g.C[z];
#pragma unroll
    for (int mt = 0; mt < 4; ++mt) {
        int row0 = bm + wm * 64 + mt * 16 + (lane >> 2);
#pragma unroll
        for (int nt = 0; nt < 4; ++nt) {
            int col = bn + wn * 32 + nt * 8 + (lane & 3) * 2;
            if (col < Nz) {
                *(float2*)(Cz + (size_t)row0 * Nz + col) =
                    make_float2(acc[mt][nt][0], acc[mt][nt][1]);
                *(float2*)(Cz + (size_t)(row0 + 8) * Nz + col) =
                    make_float2(acc[mt][nt][2], acc[mt][nt][3]);
            }
        }
    }
}

// ---------------- k_compress ------------------------------------------------
__global__ void compress_kernel(const float* __restrict__ K, float* __restrict__ KC)
{
    int idx = blockIdx.x * blockDim.x + threadIdx.x;
    if (idx >= GG * DD) return;
    int g = idx >> 10;
    int d = idx & 1023;
    float s = 0.f;
#pragma unroll 8
    for (int c = 0; c < CC; ++c)
        s += K[(size_t)(g * CC + c) * DD + d];
    KC[idx] = s * (1.0f / 64.0f);
}

// ---------------- MMA-based fused sparse attention ---------------------------
// grid (16,16), 256 threads. Warps 0-3 = consumers (16 query rows each, flash
// online softmax in registers). Warps 4-7 = producers (double-buffer K/V tiles
// with fp32->bf16 hi/lo split; V stored transposed). Intra (causal) processed
// first (its gated result stashed in smem), then the selected inter blocks.
#define QPAD 72          // bf16 stride for 64-wide tiles
#define TILEB (64 * QPAD * 2)   // 9216 bytes per bf16 tile
// smem byte offsets
#define SQH    0
#define SQL    (SQH + TILEB)
#define SBUF   (SQL + TILEB)              // 2 bufs x 4 tiles (Kh,Kl,Vh,Vl)
#define SKC    (SBUF + 8 * TILEB)         // float [16*65]
#define SSTASH (SKC + 16 * 65 * 4)        // float [64*65]
#define SSC    (SSTASH + 64 * 65 * 4)     // float [8*16]
#define SSELB  (SSC + 512)                // uint  [64]
#define SLIST  (SSELB + 256)              // int   [17]
#define SCNT   (SLIST + 68)               // int
#define SNMASK (SCNT + 4)                 // int
#define ATTN_SMEM (SNMASK + 16)

__global__ void __launch_bounds__(256) attn_mma(
    const float* __restrict__ Qg, const float* __restrict__ Kg,
    const float* __restrict__ Vg, const float* __restrict__ KC,
    const float* __restrict__ GL, float* __restrict__ O)
{
    extern __shared__ char smc[];
    const uint32_t sb = smem_u32(smc);
    __nv_bfloat16* qh = (__nv_bfloat16*)(smc + SQH);
    __nv_bfloat16* ql = (__nv_bfloat16*)(smc + SQL);
    float* kc_s   = (float*)(smc + SKC);
    float* stash  = (float*)(smc + SSTASH);
    float* sc_s   = (float*)(smc + SSC);
    uint32_t* selb = (uint32_t*)(smc + SSELB);
    int* list_s   = (int*)(smc + SLIST);
    int* cnt_s    = (int*)(smc + SCNT);
    int* nmask    = (int*)(smc + SNMASK);

    const int g = blockIdx.x;
    const int h = blockIdx.y;
    const int tid = threadIdx.x;
    const int wid = tid >> 5;
    const int lane = tid & 31;
    const float scale = 0.125f;

    if (tid == 0) *nmask = 0;

    // ---- stage Q (bf16 hi/lo) and compressed keys (fp32) ----
    for (int u = tid; u < 1024; u += 256) {
        int r = u >> 4, seg = (u & 15) << 2;
        float4 qv = *(const float4*)(Qg + (size_t)(g * 64 + r) * DD + h * 64 + seg);
        __nv_bfloat16 a0 = __float2bfloat16_rn(qv.x), a1 = __float2bfloat16_rn(qv.y);
        __nv_bfloat16 a2 = __float2bfloat16_rn(qv.z), a3 = __float2bfloat16_rn(qv.w);
        uint2 hp, lp;
        hp.x = (uint32_t)__bfloat16_as_ushort(a0) | ((uint32_t)__bfloat16_as_ushort(a1) << 16);
        hp.y = (uint32_t)__bfloat16_as_ushort(a2) | ((uint32_t)__bfloat16_as_ushort(a3) << 16);
        lp.x = (uint32_t)__bfloat16_as_ushort(__float2bfloat16_rn(qv.x - __bfloat162float(a0))) |
               ((uint32_t)__bfloat16_as_ushort(__float2bfloat16_rn(qv.y - __bfloat162float(a1))) << 16);
        lp.y = (uint32_t)__bfloat16_as_ushort(__float2bfloat16_rn(qv.z - __bfloat162float(a2))) |
               ((uint32_t)__bfloat16_as_ushort(__float2bfloat16_rn(qv.w - __bfloat162float(a3))) << 16);
        *(uint2*)(qh + r * QPAD + seg) = hp;
        *(uint2*)(ql + r * QPAD + seg) = lp;
    }
    for (int u = tid; u < 1024; u += 256) {
        int gp = u >> 6, d = u & 63;
        kc_s[gp * 65 + d] = KC[(size_t)gp * DD + h * 64 + d];
    }
    __syncthreads();

    // ---- selection (fp32, identical semantics to passing R5 kernel) ----
    for (int qq = 0; qq < 8; ++qq) {
        int qi = wid * 8 + qq;
        int gp = lane & 15;
        int half = lane >> 4;
        float part = 0.f;
#pragma unroll
        for (int d = 0; d < 32; ++d) {
            int di = half * 32 + d;
            float qv = __bfloat162float(qh[qi * QPAD + di]) +
                       __bfloat162float(ql[qi * QPAD + di]);
            part = fmaf(qv, kc_s[gp * 65 + di], part);
        }
        part += __shfl_xor_sync(0xffffffffu, part, 16);
        if (lane < 16) sc_s[wid * 16 + lane] = part;
        __syncwarp();
        float m1 = -INFINITY; int i1 = 0;
#pragma unroll
        for (int gp2 = 0; gp2 < 16; ++gp2) {
            float v = (gp2 > g) ? sc_s[wid * 16 + gp2] : -INFINITY;
            if (v > m1) { m1 = v; i1 = gp2; }
        }
        float m2 = -INFINITY; int i2 = (i1 == 0) ? 1 : 0;
#pragma unroll
        for (int gp2 = 0; gp2 < 16; ++gp2) {
            if (gp2 == i1) continue;
            float v = (gp2 > g) ? sc_s[wid * 16 + gp2] : -INFINITY;
            if (v > m2) { m2 = v; i2 = gp2; }
        }
        if (lane == 0) {
            selb[qi] = (1u << i1) | (1u << i2);
            atomicOr(nmask, (1 << i1) | (1 << i2));
        }
        __syncwarp();
    }
    __syncthreads();

    if (tid == 0) {
        int cnt = 0;
        list_s[cnt++] = g;                       // intra first
        int nm = *nmask;
        for (int jb = 0; jb < 16; ++jb)
            if (nm & (1 << jb)) list_s[cnt++] = jb;
        cnt_s[0] = cnt;
    }
    __syncthreads();
    const int ntot = cnt_s[0];

    // ---- producers stage list[0] into buffer 0 ----
    if (wid >= 4) {
        int pt = tid - 128;
        int jb = list_s[0];
        __nv_bfloat16* kh  = (__nv_bfloat16*)(smc + SBUF);
        __nv_bfloat16* kl  = kh + 64 * QPAD;
        __nv_bfloat16* vth = kl + 64 * QPAD;
        __nv_bfloat16* vtl = vth + 64 * QPAD;
        for (int u = pt; u < 1024; u += 128) {
            int c = u >> 4, seg = (u & 15) << 2;
            size_t go = (size_t)(jb * 64 + c) * DD + h * 64 + seg;
            float4 kv = *(const float4*)(Kg + go);
            __nv_bfloat16 k0 = __float2bfloat16_rn(kv.x), k1 = __float2bfloat16_rn(kv.y);
            __nv_bfloat16 k2 = __float2bfloat16_rn(kv.z), k3 = __float2bfloat16_rn(kv.w);
            uint2 hp, lp;
            hp.x = (uint32_t)__bfloat16_as_ushort(k0) | ((uint32_t)__bfloat16_as_ushort(k1) << 16);
            hp.y = (uint32_t)__bfloat16_as_ushort(k2) | ((uint32_t)__bfloat16_as_ushort(k3) << 16);
            lp.x = (uint32_t)__bfloat16_as_ushort(__float2bfloat16_rn(kv.x - __bfloat162float(k0))) |
                   ((uint32_t)__bfloat16_as_ushort(__float2bfloat16_rn(kv.y - __bfloat162float(k1))) << 16);
            lp.y = (uint32_t)__bfloat16_as_ushort(__float2bfloat16_rn(kv.z - __bfloat162float(k2))) |
                   ((uint32_t)__bfloat16_as_ushort(__float2bfloat16_rn(kv.w - __bfloat162float(k3))) << 16);
            *(uint2*)(kh + c * QPAD + seg) = hp;
            *(uint2*)(kl + c * QPAD + seg) = lp;
            float4 vv = *(const float4*)(Vg + go);
            float vf[4] = {vv.x, vv.y, vv.z, vv.w};
#pragma unroll
            for (int j = 0; j < 4; ++j) {
                __nv_bfloat16 vh = __float2bfloat16_rn(vf[j]);
                vth[(seg + j) * QPAD + c] = vh;
                vtl[(seg + j) * QPAD + c] = __float2bfloat16_rn(vf[j] - __bfloat162float(vh));
            }
        }
    }
    __syncthreads();

    // ---- main pipeline ----
    const int r0 = (wid & 3) * 16 + (lane >> 2);
    const int r1 = r0 + 8;
    const int q2 = (lane & 3) * 2;
    const int akof = (lane >> 4) << 3;
    const int arow = (wid & 3) * 16 + (lane & 15);
    const int brow = lane & 7;
    const int bkof = (lane & 8) ? 8 : 0;

    float m0 = -INFINITY, m1 = -INFINITY, l0 = 0.f, l1 = 0.f;
    float o[8][4];
#pragma unroll
    for (int nt = 0; nt < 8; ++nt)
#pragma unroll
        for (int e = 0; e < 4; ++e) o[nt][e] = 0.f;

    for (int i = 0; i < ntot; ++i) {
        if (wid >= 4) {
            if (i + 1 < ntot) {
                int pt = tid - 128;
                int jb = list_s[i + 1];
                char* bp = smc + SBUF + ((i + 1) & 1) * 4 * TILEB;
                __nv_bfloat16* kh  = (__nv_bfloat16*)bp;
                __nv_bfloat16* kl  = kh + 64 * QPAD;
                __nv_bfloat16* vth = kl + 64 * QPAD;
                __nv_bfloat16* vtl = vth + 64 * QPAD;
                for (int u = pt; u < 1024; u += 128) {
                    int c = u >> 4, seg = (u & 15) << 2;
                    size_t go = (size_t)(jb * 64 + c) * DD + h * 64 + seg;
                    float4 kv = *(const float4*)(Kg + go);
                    __nv_bfloat16 k0 = __float2bfloat16_rn(kv.x), k1 = __float2bfloat16_rn(kv.y);
                    __nv_bfloat16 k2 = __float2bfloat16_rn(kv.z), k3 = __float2bfloat16_rn(kv.w);
                    uint2 hp, lp;
                    hp.x = (uint32_t)__bfloat16_as_ushort(k0) | ((uint32_t)__bfloat16_as_ushort(k1) << 16);
                    hp.y = (uint32_t)__bfloat16_as_ushort(k2) | ((uint32_t)__bfloat16_as_ushort(k3) << 16);
                    lp.x = (uint32_t)__bfloat16_as_ushort(__float2bfloat16_rn(kv.x - __bfloat162float(k0))) |
                           ((uint32_t)__bfloat16_as_ushort(__float2bfloat16_rn(kv.y - __bfloat162float(k1))) << 16);
                    lp.y = (uint32_t)__bfloat16_as_ushort(__float2bfloat16_rn(kv.z - __bfloat162float(k2))) |
                           ((uint32_t)__bfloat16_as_ushort(__float2bfloat16_rn(kv.w - __bfloat162float(k3))) << 16);
                    *(uint2*)(kh + c * QPAD + seg) = hp;
                    *(uint2*)(kl + c * QPAD + seg) = lp;
                    float4 vv = *(const float4*)(Vg + go);
                    float vf[4] = {vv.x, vv.y, vv.z, vv.w};
#pragma unroll
                    for (int j = 0; j < 4; ++j) {
                        __nv_bfloat16 vh = __float2bfloat16_rn(vf[j]);
                        vth[(seg + j) * QPAD + c] = vh;
                        vtl[(seg + j) * QPAD + c] = __float2bfloat16_rn(vf[j] - __bfloat162float(vh));
                    }
                }
            }
        } else {
            const int jb = list_s[i];
            const bool intra = (i == 0);
            const uint32_t bK  = sb + SBUF + (uint32_t)((i & 1) * 4 * TILEB);
            const uint32_t bKl = bK + TILEB;
            const uint32_t bVh = bK + 2 * TILEB;
            const uint32_t bVl = bK + 3 * TILEB;
            const uint32_t sQh = sb + SQH, sQl = sb + SQL;

            // --- S = Q K^T (bf16x3) ---
            float s[8][4];
#pragma unroll
            for (int nt = 0; nt < 8; ++nt)
#pragma unroll
                for (int e = 0; e < 4; ++e) s[nt][e] = 0.f;
#pragma unroll
            for (int kt = 0; kt < 4; ++kt) {
                uint32_t ao = (uint32_t)((arow * QPAD + kt * 16 + akof) * 2);
                uint32_t ah[4], al[4];
                ldsm_x4(ah, sQh + ao);
                ldsm_x4(al, sQl + ao);
#pragma unroll
                for (int nt = 0; nt < 8; ++nt) {
                    uint32_t bo = (uint32_t)(((nt * 8 + brow) * QPAD + kt * 16 + bkof) * 2);
                    uint32_t bh[2], bl[2];
                    ldsm_x2(bh, bK + bo);
                    ldsm_x2(bl, bKl + bo);
                    mma16816(s[nt], ah, bh);
                    mma16816(s[nt], ah, bl);
                    mma16816(s[nt], al, bh);
                }
            }
            // --- scale + mask ---
            const uint32_t sb0 = selb[r0], sb1 = selb[r1];
#pragma unroll
            for (int nt = 0; nt < 8; ++nt) {
                int c0 = nt * 8 + q2, c1 = c0 + 1;
                bool v00, v01, v10, v11;
                if (intra) {
                    v00 = c0 <= r0; v01 = c1 <= r0;
                    v10 = c0 <= r1; v11 = c1 <= r1;
                } else {
                    bool a = (sb0 >> jb) & 1, b = (sb1 >> jb) & 1;
                    v00 = a; v01 = a; v10 = b; v11 = b;
                }
                s[nt][0] = v00 ? s[nt][0] * scale : -INFINITY;
                s[nt][1] = v01 ? s[nt][1] * scale : -INFINITY;
                s[nt][2] = v10 ? s[nt][2] * scale : -INFINITY;
                s[nt][3] = v11 ? s[nt][3] * scale : -INFINITY;
            }
            // --- online softmax ---
            float mx0 = -INFINITY, mx1 = -INFINITY;
#pragma unroll
            for (int nt = 0; nt < 8; ++nt) {
                mx0 = fmaxf(mx0, fmaxf(s[nt][0], s[nt][1]));
                mx1 = fmaxf(mx1, fmaxf(s[nt][2], s[nt][3]));
            }
            mx0 = fmaxf(mx0, __shfl_xor_sync(0xffffffffu, mx0, 1));
            mx0 = fmaxf(mx0, __shfl_xor_sync(0xffffffffu, mx0, 2));
            mx1 = fmaxf(mx1, __shfl_xor_sync(0xffffffffu, mx1, 1));
            mx1 = fmaxf(mx1, __shfl_xor_sync(0xffffffffu, mx1, 2));
            float mn0 = fmaxf(m0, mx0), mn1 = fmaxf(m1, mx1);
            float al0 = (mn0 == -INFINITY) ? 0.f : __expf(m0 - mn0);
            float al1 = (mn1 == -INFINITY) ? 0.f : __expf(m1 - mn1);
            float rs0 = 0.f, rs1 = 0.f;
            uint32_t pha[4][4], pla[4][4];
#pragma unroll
            for (int nt = 0; nt < 8; ++nt) {
                float p0 = (mn0 == -INFINITY) ? 0.f : __expf(s[nt][0] - mn0);
                float p1 = (mn0 == -INFINITY) ? 0.f : __expf(s[nt][1] - mn0);
                float p2 = (mn1 == -INFINITY) ? 0.f : __expf(s[nt][2] - mn1);
                float p3 = (mn1 == -INFINITY) ? 0.f : __expf(s[nt][3] - mn1);
                rs0 += p0 + p1;
                rs1 += p2 + p3;
                int kt = nt >> 1, hf = nt & 1;
                __nv_bfloat16 b0 = __float2bfloat16_rn(p0), b1 = __float2bfloat16_rn(p1);
                __nv_bfloat16 b2 = __float2bfloat16_rn(p2), b3 = __float2bfloat16_rn(p3);
                pha[kt][hf * 2 + 0] = (uint32_t)__bfloat16_as_ushort(b0) |
                                      ((uint32_t)__bfloat16_as_ushort(b1) << 16);
                pha[kt][hf * 2 + 1] = (uint32_t)__bfloat16_as_ushort(b2) |
                                      ((uint32_t)__bfloat16_as_ushort(b3) << 16);
                pla[kt][hf * 2 + 0] = packbf(p0 - __bfloat162float(b0), p1 - __bfloat162float(b1));
                pla[kt][hf * 2 + 1] = packbf(p2 - __bfloat162float(b2), p3 - __bfloat162float(b3));
            }
            rs0 += __shfl_xor_sync(0xffffffffu, rs0, 1);
            rs0 += __shfl_xor_sync(0xffffffffu, rs0, 2);
            rs1 += __shfl_xor_sync(0xffffffffu, rs1, 1);
            rs1 += __shfl_xor_sync(0xffffffffu, rs1, 2);
            l0 = l0 * al0 + rs0;
            l1 = l1 * al1 + rs1;
#pragma unroll
            for (int nt = 0; nt < 8; ++nt) {
                o[nt][0] *= al0; o[nt][1] *= al0;
                o[nt][2] *= al1; o[nt][3] *= al1;
            }
            // --- O += P V (bf16x3) ---
#pragma unroll
            for (int kt = 0; kt < 4; ++kt) {
#pragma unroll
                for (int nt = 0; nt < 8; ++nt) {
                    uint32_t bo = (uint32_t)(((nt * 8 + brow) * QPAD + kt * 16 + bkof) * 2);
                    uint32_t bh[2], bl[2];
                    ldsm_x2(bh, bVh + bo);
                    ldsm_x2(bl, bVl + bo);
                    mma16816(o[nt], pha[kt], bh);
                    mma16816(o[nt], pha[kt], bl);
                    mma16816(o[nt], pla[kt], bh);
                }
            }
            m0 = mn0; m1 = mn1;

            if (intra) {
                // finalize intra: stash g1 * o / l, reset state
                int n0 = g * 64 + r0, n1 = g * 64 + r1;
                float ga0 = GL[(size_t)n0 * 32 + 2 * h], gb0 = GL[(size_t)n0 * 32 + 2 * h + 1];
                float ga1 = GL[(size_t)n1 * 32 + 2 * h], gb1 = GL[(size_t)n1 * 32 + 2 * h + 1];
                float mg0 = fmaxf(ga0, gb0), mg1 = fmaxf(ga1, gb1);
                float e00 = __expf(ga0 - mg0), e01 = __expf(gb0 - mg0);
                float e10 = __expf(ga1 - mg1), e11 = __expf(gb1 - mg1);
                float iv0 = (e01 / (e00 + e01)) / l0;
                float iv1 = (e11 / (e10 + e11)) / l1;
#pragma unroll
                for (int nt = 0; nt < 8; ++nt) {
                    int c = nt * 8 + q2;
                    stash[r0 * 65 + c]     = o[nt][0] * iv0;
                    stash[r0 * 65 + c + 1] = o[nt][1] * iv0;
                    stash[r1 * 65 + c]     = o[nt][2] * iv1;
                    stash[r1 * 65 + c + 1] = o[nt][3] * iv1;
                }
                m0 = -INFINITY; m1 = -INFINITY; l0 = 0.f; l1 = 0.f;
#pragma unroll
                for (int nt = 0; nt < 8; ++nt)
#pragma unroll
                    for (int e = 0; e < 4; ++e) o[nt][e] = 0.f;
            }
        }
        __syncthreads();
    }

    // ---- epilogue: blend inter + stashed intra, write O ----
    if (wid < 4) {
        int n0 = g * 64 + r0, n1 = g * 64 + r1;
        float ga0 = GL[(size_t)n0 * 32 + 2 * h], gb0 = GL[(size_t)n0 * 32 + 2 * h + 1];
        float ga1 = GL[(size_t)n1 * 32 + 2 * h], gb1 = GL[(size_t)n1 * 32 + 2 * h + 1];
        float mg0 = fmaxf(ga0, gb0), mg1 = fmaxf(ga1, gb1);
        float e00 = __expf(ga0 - mg0), e01 = __expf(gb0 - mg0);
        float e10 = __expf(ga1 - mg1), e11 = __expf(gb1 - mg1);
        float iv0 = (e00 / (e00 + e01)) / l0;
        float iv1 = (e10 / (e10 + e11)) / l1;
#pragma unroll
        for (int nt = 0; nt < 8; ++nt) {
            int c = nt * 8 + q2;
            float v0 = o[nt][0] * iv0 + stash[r0 * 65 + c];
            float v1 = o[nt][1] * iv0 + stash[r0 * 65 + c + 1];
            float v2 = o[nt][2] * iv1 + stash[r1 * 65 + c];
            float v3 = o[nt][3] * iv1 + stash[r1 * 65 + c + 1];
            *(float2*)(O + (size_t)n0 * DD + h * 64 + c) = make_float2(v0, v1);
            *(float2*)(O + (size_t)n1 * DD + h * 64 + c) = make_float2(v2, v3);
        }
    }
}

// ---------------- launch -----------------------------------------------------
extern "C" void kernel_launch(void* const* d_in, const int* in_sizes, int n_in,
                              void* d_out, int out_size)
{
    const float* x  = (const float*)d_in[0];
    const float* Wq = (const float*)d_in[1];
    const float* Wk = (const float*)d_in[2];
    const float* Wv = (const float*)d_in[3];
    const float* Wg = (const float*)d_in[4];
    const float* Wo = (const float*)d_in[5];
    float* out = (float*)d_out;

    float *Q, *K, *V, *GL, *KC, *O;
    cudaGetSymbolAddress((void**)&Q,  d_Q);
    cudaGetSymbolAddress((void**)&K,  d_K);
    cudaGetSymbolAddress((void**)&V,  d_V);
    cudaGetSymbolAddress((void**)&GL, d_GL);
    cudaGetSymbolAddress((void**)&KC, d_KC);
    cudaGetSymbolAddress((void**)&O,  d_O);

    __nv_bfloat16 *xh, *xl, *qh, *ql, *kh, *kl, *vh, *vl, *oh, *ol, *gh, *gl2, *obh, *obl;
    cudaGetSymbolAddress((void**)&xh,  sx_hi);  cudaGetSymbolAddress((void**)&xl,  sx_lo);
    cudaGetSymbolAddress((void**)&qh,  swq_hi); cudaGetSymbolAddress((void**)&ql,  swq_lo);
    cudaGetSymbolAddress((void**)&kh,  swk_hi); cudaGetSymbolAddress((void**)&kl,  swk_lo);
    cudaGetSymbolAddress((void**)&vh,  swv_hi); cudaGetSymbolAddress((void**)&vl,  swv_lo);
    cudaGetSymbolAddress((void**)&oh,  swo_hi); cudaGetSymbolAddress((void**)&ol,  swo_lo);
    cudaGetSymbolAddress((void**)&gh,  swg_hi); cudaGetSymbolAddress((void**)&gl2, swg_lo);
    cudaGetSymbolAddress((void**)&obh, so_hi);  cudaGetSymbolAddress((void**)&obl, so_lo);

    // 1) split-convert x + all weights
    ConvArgs ca;
    ca.src[0] = x;  ca.hi[0] = xh;  ca.lo[0] = xl;  ca.n[0] = NN * DD;
    ca.src[1] = Wq; ca.hi[1] = qh;  ca.lo[1] = ql;  ca.n[1] = DD * DD;
    ca.src[2] = Wk; ca.hi[2] = kh;  ca.lo[2] = kl;  ca.n[2] = DD * DD;
    ca.src[3] = Wv; ca.hi[3] = vh;  ca.lo[3] = vl;  ca.n[3] = DD * DD;
    ca.src[4] = Wg; ca.hi[4] = gh;  ca.lo[4] = gl2; ca.n[4] = 32 * DD;
    ca.src[5] = Wo; ca.hi[5] = oh;  ca.lo[5] = ol;  ca.n[5] = DD * DD;
    convert_kernel<<<dim3(1024, 6), 256>>>(ca);

    // 2) QKV + gate projections
    GemmArgs gq;
    gq.Ahi = xh; gq.Alo = xl;
    gq.Bhi[0] = qh; gq.Blo[0] = ql;  gq.C[0] = Q;  gq.N[0] = DD;
    gq.Bhi[1] = kh; gq.Blo[1] = kl;  gq.C[1] = K;  gq.N[1] = DD;
    gq.Bhi[2] = vh; gq.Blo[2] = vl;  gq.C[2] = V;  gq.N[2] = DD;
    gq.Bhi[3] = gh; gq.Blo[3] = gl2; gq.C[3] = GL; gq.N[3] = 32;
    mma_gemm<<<dim3(8, 8, 4), 256>>>(gq);

    // 3) compressed block keys
    compress_kernel<<<(GG * DD + 255) / 256, 256>>>(K, KC);

    // 4) fused sparse attention (tensor-core flash)
    cudaFuncSetAttribute(attn_mma, cudaFuncAttributeMaxDynamicSharedMemorySize, ATTN_SMEM);
    attn_mma<<<dim3(GG, HH), 256, ATTN_SMEM>>>(Q, K, V, KC, GL, O);

    // 5) split-convert O
    ConvArgs co;
    co.src[0] = O; co.hi[0] = obh; co.lo[0] = obl; co.n[0] = NN * DD;
    for (int i = 1; i < 6; ++i) { co.src[i] = O; co.hi[i] = obh; co.lo[i] = obl; co.n[i] = 0; }
    convert_kernel<<<dim3(1024, 1), 256>>>(co);

    // 6) output projection
    GemmArgs go;
    go.Ahi = obh; go.Alo = obl;
    go.Bhi[0] = oh; go.Blo[0] = ol; go.C[0] = out; go.N[0] = DD;
    for (int i = 1; i < 4; ++i) { go.Bhi[i] = oh; go.Blo[i] = ol; go.C[i] = out; go.N[i] = 0; }
    mma_gemm<<<dim3(8, 8, 1), 256>>>(go);
}